// round 2
// baseline (speedup 1.0000x reference)
#include <cuda_runtime.h>
#include <cuda_fp16.h>

#define RD 8192
#define HD 256

// ---- static device scratch (no allocations) ----
__device__ float d_h[RD*HD];
__device__ float d_G[RD*1536];
__device__ float d_y2[RD*128];
__device__ unsigned d_Ahi[512*16*32*4];
__device__ unsigned d_Alo[512*16*32*4];
__device__ unsigned d_Y1hi[512*8*32*4];
__device__ unsigned d_Y1lo[512*8*32*4];
__device__ uint2 d_WGhi[192*16*32];
__device__ uint2 d_WGlo[192*16*32];
__device__ uint2 d_W1hi[16*16*32];
__device__ uint2 d_W1lo[16*16*32];
__device__ uint2 d_W2hi[16*8*32];
__device__ uint2 d_W2lo[16*8*32];
__device__ float d_Mi[768*2];
__device__ float d_ci[768];
__device__ unsigned char d_use[20*64];
__device__ int d_epsMode;

// ---- helpers ----
__device__ __forceinline__ unsigned packsplit(float v0, float v1, unsigned &lo) {
    __half h0 = __float2half(v0);
    __half h1 = __float2half(v1);
    __half l0 = __float2half(v0 - __half2float(h0));
    __half l1 = __float2half(v1 - __half2float(h1));
    lo = ((unsigned)__half_as_ushort(l1) << 16) | (unsigned)__half_as_ushort(l0);
    return ((unsigned)__half_as_ushort(h1) << 16) | (unsigned)__half_as_ushort(h0);
}
__device__ __forceinline__ int fidx(int r, int c, int KT) {
    return (((r >> 4) * KT + (c >> 4)) * 32 + (r & 7) * 4 + ((c & 7) >> 1)) * 4
           + ((r >> 3) & 1) + (((c >> 3) & 1) << 1);
}
__device__ __forceinline__ void mma16816(float (&c)[4], const uint4 a, const uint2 b) {
    asm volatile(
        "mma.sync.aligned.m16n8k16.row.col.f32.f16.f16.f32 "
        "{%0,%1,%2,%3},{%4,%5,%6,%7},{%8,%9},{%0,%1,%2,%3};\n"
        : "+f"(c[0]), "+f"(c[1]), "+f"(c[2]), "+f"(c[3])
        : "r"(a.x), "r"(a.y), "r"(a.z), "r"(a.w), "r"(b.x), "r"(b.y));
}
__device__ __forceinline__ float eluf(float x) { return x > 0.f ? x : expm1f(x); }

// ---- setup ----
__global__ void s_init() {
    int i = blockIdx.x * 256 + threadIdx.x;
    if (i < RD*HD) d_h[i] = 0.f;
    if (i < 512*16*32*4) { d_Ahi[i] = 0u; d_Alo[i] = 0u; }
}

__global__ void s_detect(const unsigned char* eps) {
    if (threadIdx.x == 0 && blockIdx.x == 0) {
        int ones3f = 0, nz123 = 0;
        for (int i = 0; i < 768; i++) {
            unsigned char b = eps[i];
            if ((i & 3) == 3 && b == 0x3f) ones3f++;
            if ((i & 3) != 0 && b != 0) nz123++;
        }
        d_epsMode = (ones3f > 0) ? 2 : (nz123 == 0 ? 1 : 0);
    }
}

__global__ void s_pack(const float* __restrict__ wh, const float* __restrict__ wi,
                       const float* __restrict__ w1, const float* __restrict__ w2,
                       const float* __restrict__ ew, const float* __restrict__ eb,
                       const float* __restrict__ bi, const unsigned char* __restrict__ eps) {
    int id = blockIdx.x * 256 + threadIdx.x;
    if (id < 98304) {                      // WG = [Wh(768); Wi(768)] x 256
        int lane = id & 31, kt = (id >> 5) & 15, nt = id >> 9;
        int n = nt * 8 + (lane >> 2);
        const float* src = (n < 768) ? (wh + n * 256) : (wi + (n - 768) * 256);
        int k0 = kt * 16 + (lane & 3) * 2;
        uint2 H, L;
        H.x = packsplit(src[k0],   src[k0+1], L.x);
        H.y = packsplit(src[k0+8], src[k0+9], L.y);
        d_WGhi[id] = H; d_WGlo[id] = L;
    } else if (id < 106496) {              // W1: [128,256]
        int j = id - 98304;
        int lane = j & 31, kt = (j >> 5) & 15, nt = j >> 9;
        const float* src = w1 + (nt * 8 + (lane >> 2)) * 256;
        int k0 = kt * 16 + (lane & 3) * 2;
        uint2 H, L;
        H.x = packsplit(src[k0],   src[k0+1], L.x);
        H.y = packsplit(src[k0+8], src[k0+9], L.y);
        d_W1hi[j] = H; d_W1lo[j] = L;
    } else if (id < 110592) {              // W2: [128,128]
        int j = id - 106496;
        int lane = j & 31, kt = (j >> 5) & 7, nt = j >> 8;
        const float* src = w2 + (nt * 8 + (lane >> 2)) * 128;
        int k0 = kt * 16 + (lane & 3) * 2;
        uint2 H, L;
        H.x = packsplit(src[k0],   src[k0+1], L.x);
        H.y = packsplit(src[k0+8], src[k0+9], L.y);
        d_W2hi[j] = H; d_W2lo[j] = L;
    } else if (id < 111360) {              // Mi = Wi@embed_w, ci = Wi@embed_b + bi
        int n = id - 110592;
        const float* wr = wi + n * 256;
        float m0 = 0.f, m1 = 0.f, cc = 0.f;
        for (int k = 0; k < 256; k++) {
            float v = wr[k];
            m0 += v * ew[2*k]; m1 += v * ew[2*k+1]; cc += v * eb[k];
        }
        d_Mi[2*n] = m0; d_Mi[2*n+1] = m1; d_ci[n] = cc + bi[n];
    } else if (id < 112640) {              // d_use[t][a]
        int j = id - 111360;
        int t = j >> 6, a = j & 63;
        unsigned char u = 0;
        if (t >= 8) {
            int m = (t - 8) * 64 + a;
            int mode = d_epsMode;
            float v = (mode == 2) ? ((const float*)eps)[m]
                    : (mode == 1) ? (float)((const int*)eps)[m]
                    : (float)eps[m];
            u = (v != 0.f) ? 1 : 0;
        }
        d_use[j] = u;
    }
}

// ---- GRU GEMM: G[:,0:768] = h@Wh^T always; G[:,768:1536] = h@Wi^T for masked agents ----
__global__ void __launch_bounds__(256) k_gemm(int t) {
    int am = blockIdx.x;
    int n0 = blockIdx.y << 6;
    if (n0 >= 768 && !d_use[t * 64 + am]) return;
    int lane = threadIdx.x & 31, w = threadIdx.x >> 5;
    int wm = w & 1, wn = w >> 1;
    float acc[4][2][4];
#pragma unroll
    for (int i = 0; i < 4; i++)
#pragma unroll
        for (int j = 0; j < 2; j++)
#pragma unroll
            for (int q = 0; q < 4; q++) acc[i][j][q] = 0.f;
    int mtb = am * 8 + wm * 4;
    int ntb = (n0 >> 3) + wn * 2;
#pragma unroll 1
    for (int kt = 0; kt < 16; kt++) {
        uint4 ah[4], al[4];
#pragma unroll
        for (int i = 0; i < 4; i++) {
            int base = (((mtb + i) * 16 + kt) * 32 + lane) * 4;
            ah[i] = *(const uint4*)(d_Ahi + base);
            al[i] = *(const uint4*)(d_Alo + base);
        }
#pragma unroll
        for (int j = 0; j < 2; j++) {
            int bb = ((ntb + j) * 16 + kt) * 32 + lane;
            uint2 Bh = d_WGhi[bb], Bl = d_WGlo[bb];
#pragma unroll
            for (int i = 0; i < 4; i++) {
                mma16816(acc[i][j], ah[i], Bh);
                mma16816(acc[i][j], al[i], Bh);
                mma16816(acc[i][j], ah[i], Bl);
            }
        }
    }
    int r0 = am * 128 + wm * 64 + (lane >> 2);
    int c0 = n0 + wn * 16 + (lane & 3) * 2;
#pragma unroll
    for (int i = 0; i < 4; i++)
#pragma unroll
        for (int j = 0; j < 2; j++) {
            float* g = d_G + (size_t)(r0 + i * 16) * 1536 + c0 + j * 8;
            g[0] = acc[i][j][0]; g[1] = acc[i][j][1];
            g[1536*8] = acc[i][j][2]; g[1536*8 + 1] = acc[i][j][3];
        }
}

// ---- GRU gates + h update; writes h as fp32 and as packed A fragments ----
__global__ void __launch_bounds__(256) k_gate(const float* __restrict__ inp,
                                              const float* __restrict__ bh,
                                              const float* __restrict__ bi, int t) {
    int id = blockIdx.x * 256 + threadIdx.x;
    int r = id >> 7;
    int cp = (id & 127) << 1;
    int a = r >> 7, b = r & 127;
    int useh = d_use[t * 64 + a];
    const float* ip = inp + ((b * 64 + a) * 20 + t) * 2;
    float in0 = ip[0], in1 = ip[1];
    const float* Gr = d_G + (size_t)r * 1536;
    float hv[2];
#pragma unroll
    for (int q = 0; q < 2; q++) {
        int c = cp + q;
        float hr = Gr[c] + bh[c];
        float hz = Gr[256 + c] + bh[256 + c];
        float hn = Gr[512 + c] + bh[512 + c];
        float ir, iz, in_;
        if (useh) {
            ir  = Gr[768 + c]  + bi[c];
            iz  = Gr[1024 + c] + bi[256 + c];
            in_ = Gr[1280 + c] + bi[512 + c];
        } else {
            ir  = in0 * d_Mi[2*c]         + in1 * d_Mi[2*c + 1]         + d_ci[c];
            iz  = in0 * d_Mi[2*(256+c)]   + in1 * d_Mi[2*(256+c) + 1]   + d_ci[256 + c];
            in_ = in0 * d_Mi[2*(512+c)]   + in1 * d_Mi[2*(512+c) + 1]   + d_ci[512 + c];
        }
        float rg = 1.f / (1.f + expf(-(ir + hr)));
        float zg = 1.f / (1.f + expf(-(iz + hz)));
        float ng = tanhf(in_ + rg * hn);
        float ho = d_h[r * HD + c];
        hv[q] = (1.f - zg) * ng + zg * ho;
        d_h[r * HD + c] = hv[q];
    }
    unsigned lo, hi = packsplit(hv[0], hv[1], lo);
    int widx = fidx(r, cp, 16);
    d_Ahi[widx] = hi; d_Alo[widx] = lo;
}

// ---- fc1: y1 = elu(h@W1^T + b1), output packed as A fragments (K=128) ----
__global__ void __launch_bounds__(256) k_fc1(const float* __restrict__ b1) {
    int lane = threadIdx.x & 31, w = threadIdx.x >> 5;
    int wm = w & 3, wn = w >> 2;
    float acc[2][8][4];
#pragma unroll
    for (int i = 0; i < 2; i++)
#pragma unroll
        for (int j = 0; j < 8; j++)
#pragma unroll
            for (int q = 0; q < 4; q++) acc[i][j][q] = 0.f;
    int mtb = blockIdx.x * 8 + wm * 2;
    int ntb = wn * 8;
#pragma unroll 1
    for (int kt = 0; kt < 16; kt++) {
        uint4 ah[2], al[2];
#pragma unroll
        for (int i = 0; i < 2; i++) {
            int base = (((mtb + i) * 16 + kt) * 32 + lane) * 4;
            ah[i] = *(const uint4*)(d_Ahi + base);
            al[i] = *(const uint4*)(d_Alo + base);
        }
#pragma unroll
        for (int j = 0; j < 8; j++) {
            int bb = ((ntb + j) * 16 + kt) * 32 + lane;
            uint2 Bh = d_W1hi[bb], Bl = d_W1lo[bb];
#pragma unroll
            for (int i = 0; i < 2; i++) {
                mma16816(acc[i][j], ah[i], Bh);
                mma16816(acc[i][j], al[i], Bh);
                mma16816(acc[i][j], ah[i], Bl);
            }
        }
    }
    int r0 = blockIdx.x * 128 + wm * 32 + (lane >> 2);
#pragma unroll
    for (int i = 0; i < 2; i++)
#pragma unroll
        for (int j = 0; j < 8; j++) {
            int rr = r0 + i * 16;
            int cc = wn * 64 + j * 8 + (lane & 3) * 2;
            float v0 = eluf(acc[i][j][0] + b1[cc]);
            float v1 = eluf(acc[i][j][1] + b1[cc + 1]);
            unsigned lo, hi = packsplit(v0, v1, lo);
            int widx = fidx(rr, cc, 8);
            d_Y1hi[widx] = hi; d_Y1lo[widx] = lo;
            v0 = eluf(acc[i][j][2] + b1[cc]);
            v1 = eluf(acc[i][j][3] + b1[cc + 1]);
            hi = packsplit(v0, v1, lo);
            widx = fidx(rr + 8, cc, 8);
            d_Y1hi[widx] = hi; d_Y1lo[widx] = lo;
        }
}

// ---- fc2: y2 = elu(y1@W2^T + b2), fp32 output ----
__global__ void __launch_bounds__(256) k_fc2(const float* __restrict__ b2) {
    int lane = threadIdx.x & 31, w = threadIdx.x >> 5;
    int wm = w & 3, wn = w >> 2;
    float acc[2][8][4];
#pragma unroll
    for (int i = 0; i < 2; i++)
#pragma unroll
        for (int j = 0; j < 8; j++)
#pragma unroll
            for (int q = 0; q < 4; q++) acc[i][j][q] = 0.f;
    int mtb = blockIdx.x * 8 + wm * 2;
    int ntb = wn * 8;
#pragma unroll 1
    for (int kt = 0; kt < 8; kt++) {
        uint4 ah[2], al[2];
#pragma unroll
        for (int i = 0; i < 2; i++) {
            int base = (((mtb + i) * 8 + kt) * 32 + lane) * 4;
            ah[i] = *(const uint4*)(d_Y1hi + base);
            al[i] = *(const uint4*)(d_Y1lo + base);
        }
#pragma unroll
        for (int j = 0; j < 8; j++) {
            int bb = ((ntb + j) * 8 + kt) * 32 + lane;
            uint2 Bh = d_W2hi[bb], Bl = d_W2lo[bb];
#pragma unroll
            for (int i = 0; i < 2; i++) {
                mma16816(acc[i][j], ah[i], Bh);
                mma16816(acc[i][j], al[i], Bh);
                mma16816(acc[i][j], ah[i], Bl);
            }
        }
    }
    int r0 = blockIdx.x * 128 + wm * 32 + (lane >> 2);
#pragma unroll
    for (int i = 0; i < 2; i++)
#pragma unroll
        for (int j = 0; j < 8; j++) {
            int rr = r0 + i * 16;
            int cc = wn * 64 + j * 8 + (lane & 3) * 2;
            d_y2[rr * 128 + cc]           = eluf(acc[i][j][0] + b2[cc]);
            d_y2[rr * 128 + cc + 1]       = eluf(acc[i][j][1] + b2[cc + 1]);
            d_y2[(rr + 8) * 128 + cc]     = eluf(acc[i][j][2] + b2[cc]);
            d_y2[(rr + 8) * 128 + cc + 1] = eluf(acc[i][j][3] + b2[cc + 1]);
        }
}

// ---- fc3 + gt mask + output ----
__global__ void __launch_bounds__(256) k_fc3(const float* __restrict__ w3,
                                             const float* __restrict__ b3,
                                             const float* __restrict__ inp,
                                             float* __restrict__ out, int t) {
    int id = blockIdx.x * 256 + threadIdx.x;
    if (id >= RD * 2) return;
    int r = id >> 1, c = id & 1;
    const float* y = d_y2 + r * 128;
    const float* w = w3 + c * 128;
    float s = b3[c];
#pragma unroll 8
    for (int k = 0; k < 128; k++) s += y[k] * w[k];
    int a = r >> 7, b = r & 127;
    float gv = inp[((b * 64 + a) * 20 + t) * 2 + c];
    out[((b * 64 + a) * 12 + (t - 8)) * 2 + c] = (gv != 0.f) ? s : 0.f;
}

extern "C" void kernel_launch(void* const* d_in, const int* in_sizes, int n_in,
                              void* d_out, int out_size) {
    // hedge: context_frame_num scalar may or may not be passed as d_in[1]
    int sh = (n_in >= 15 && in_sizes[1] <= 4) ? 0 : -1;
    const float* inputs = (const float*)d_in[0];
    const unsigned char* eps = (const unsigned char*)d_in[2 + sh];
    const float* ew = (const float*)d_in[3 + sh];
    const float* eb = (const float*)d_in[4 + sh];
    const float* wi = (const float*)d_in[5 + sh];
    const float* wh = (const float*)d_in[6 + sh];
    const float* bi = (const float*)d_in[7 + sh];
    const float* bh = (const float*)d_in[8 + sh];
    const float* w1 = (const float*)d_in[9 + sh];
    const float* b1 = (const float*)d_in[10 + sh];
    const float* w2 = (const float*)d_in[11 + sh];
    const float* b2 = (const float*)d_in[12 + sh];
    const float* w3 = (const float*)d_in[13 + sh];
    const float* b3 = (const float*)d_in[14 + sh];
    float* out = (float*)d_out;

    s_init<<<8192, 256>>>();
    s_detect<<<1, 32>>>(eps);
    s_pack<<<440, 256>>>(wh, wi, w1, w2, ew, eb, bi, eps);

    for (int t = 0; t < 20; t++) {
        int pred = (t >= 8);
        dim3 g(64, pred ? 24 : 12);
        k_gemm<<<g, 256>>>(t);
        k_gate<<<4096, 256>>>(inputs, bh, bi, t);
        if (pred) {
            k_fc1<<<64, 256>>>(b1);
            k_fc2<<<64, 256>>>(b2);
            k_fc3<<<64, 256>>>(w3, b3, inputs, out, t);
        }
    }
}

// round 3
// speedup vs baseline: 1.2728x; 1.2728x over previous
#include <cuda_runtime.h>
#include <cuda_fp16.h>

#define RD 8192

// ---- static device scratch ----
__device__ float d_h[RD*256];
__device__ unsigned d_Ahi[2][512*16*32*4];   // double-buffered h fragments (hi)
__device__ unsigned d_Alo[2][512*16*32*4];   // (lo)
__device__ uint2 d_WGhi[192*16*32];
__device__ uint2 d_WGlo[192*16*32];
__device__ uint2 d_W1hi[16*16*32];
__device__ uint2 d_W1lo[16*16*32];
__device__ uint2 d_W2hi[16*8*32];
__device__ uint2 d_W2lo[16*8*32];
__device__ float d_Mi[768*2];
__device__ float d_ci[768];
__device__ unsigned char d_use[20*64];
__device__ int d_epsMode;

// ---- helpers ----
__device__ __forceinline__ unsigned packsplit(float v0, float v1, unsigned &lo) {
    __half h0 = __float2half(v0);
    __half h1 = __float2half(v1);
    __half l0 = __float2half(v0 - __half2float(h0));
    __half l1 = __float2half(v1 - __half2float(h1));
    lo = ((unsigned)__half_as_ushort(l1) << 16) | (unsigned)__half_as_ushort(l0);
    return ((unsigned)__half_as_ushort(h1) << 16) | (unsigned)__half_as_ushort(h0);
}
__device__ __forceinline__ int fidx(int r, int c, int KT) {
    return (((r >> 4) * KT + (c >> 4)) * 32 + (r & 7) * 4 + ((c & 7) >> 1)) * 4
           + ((r >> 3) & 1) + (((c >> 3) & 1) << 1);
}
__device__ __forceinline__ void mma16816(float (&c)[4], const uint4 a, const uint2 b) {
    asm volatile(
        "mma.sync.aligned.m16n8k16.row.col.f32.f16.f16.f32 "
        "{%0,%1,%2,%3},{%4,%5,%6,%7},{%8,%9},{%0,%1,%2,%3};\n"
        : "+f"(c[0]), "+f"(c[1]), "+f"(c[2]), "+f"(c[3])
        : "r"(a.x), "r"(a.y), "r"(a.z), "r"(a.w), "r"(b.x), "r"(b.y));
}
__device__ __forceinline__ float sigf(float x) {
    return __fdividef(1.f, 1.f + __expf(-x));
}
__device__ __forceinline__ float tanh_f(float x) {
    return 2.f * sigf(2.f * x) - 1.f;
}
__device__ __forceinline__ float eluf(float x) { return x > 0.f ? x : (__expf(x) - 1.f); }

// ---- setup ----
__global__ void s_init() {
    int i = blockIdx.x * 256 + threadIdx.x;
    if (i < RD*256) d_h[i] = 0.f;
    if (i < 512*16*32*4) { d_Ahi[0][i] = 0u; d_Alo[0][i] = 0u; }
}

__global__ void s_detect(const unsigned char* eps) {
    if (threadIdx.x == 0 && blockIdx.x == 0) {
        int ones3f = 0, nz123 = 0;
        for (int i = 0; i < 768; i++) {
            unsigned char b = eps[i];
            if ((i & 3) == 3 && b == 0x3f) ones3f++;
            if ((i & 3) != 0 && b != 0) nz123++;
        }
        d_epsMode = (ones3f > 0) ? 2 : (nz123 == 0 ? 1 : 0);
    }
}

__global__ void s_pack(const float* __restrict__ wh, const float* __restrict__ wi,
                       const float* __restrict__ w1, const float* __restrict__ w2,
                       const float* __restrict__ ew, const float* __restrict__ eb,
                       const float* __restrict__ bi, const unsigned char* __restrict__ eps) {
    int id = blockIdx.x * 256 + threadIdx.x;
    if (id < 98304) {                      // WG = [Wh(768); Wi(768)] x 256
        int lane = id & 31, kt = (id >> 5) & 15, nt = id >> 9;
        int n = nt * 8 + (lane >> 2);
        const float* src = (n < 768) ? (wh + n * 256) : (wi + (n - 768) * 256);
        int k0 = kt * 16 + (lane & 3) * 2;
        uint2 H, L;
        H.x = packsplit(src[k0],   src[k0+1], L.x);
        H.y = packsplit(src[k0+8], src[k0+9], L.y);
        d_WGhi[id] = H; d_WGlo[id] = L;
    } else if (id < 106496) {              // W1: [128,256]
        int j = id - 98304;
        int lane = j & 31, kt = (j >> 5) & 15, nt = j >> 9;
        const float* src = w1 + (nt * 8 + (lane >> 2)) * 256;
        int k0 = kt * 16 + (lane & 3) * 2;
        uint2 H, L;
        H.x = packsplit(src[k0],   src[k0+1], L.x);
        H.y = packsplit(src[k0+8], src[k0+9], L.y);
        d_W1hi[j] = H; d_W1lo[j] = L;
    } else if (id < 110592) {              // W2: [128,128]
        int j = id - 106496;
        int lane = j & 31, kt = (j >> 5) & 7, nt = j >> 8;
        const float* src = w2 + (nt * 8 + (lane >> 2)) * 128;
        int k0 = kt * 16 + (lane & 3) * 2;
        uint2 H, L;
        H.x = packsplit(src[k0],   src[k0+1], L.x);
        H.y = packsplit(src[k0+8], src[k0+9], L.y);
        d_W2hi[j] = H; d_W2lo[j] = L;
    } else if (id < 111360) {              // Mi = Wi@embed_w, ci = Wi@embed_b + bi
        int n = id - 110592;
        const float* wr = wi + n * 256;
        float m0 = 0.f, m1 = 0.f, cc = 0.f;
        for (int k = 0; k < 256; k++) {
            float v = wr[k];
            m0 += v * ew[2*k]; m1 += v * ew[2*k+1]; cc += v * eb[k];
        }
        d_Mi[2*n] = m0; d_Mi[2*n+1] = m1; d_ci[n] = cc + bi[n];
    } else if (id < 112640) {              // d_use[t][a]
        int j = id - 111360;
        int t = j >> 6, a = j & 63;
        unsigned char u = 0;
        if (t >= 8) {
            int m = (t - 8) * 64 + a;
            int mode = d_epsMode;
            float v = (mode == 2) ? ((const float*)eps)[m]
                    : (mode == 1) ? (float)((const int*)eps)[m]
                    : (float)eps[m];
            u = (v != 0.f) ? 1 : 0;
        }
        d_use[j] = u;
    }
}

// ---- fused GRU step: gemm (3 or 6 chunks) + gates + h update + fragment repack ----
__global__ void __launch_bounds__(256) k_step(const float* __restrict__ inp,
                                              const float* __restrict__ bh,
                                              const float* __restrict__ bi,
                                              int t, int rb) {
    int am = blockIdx.x, cg = blockIdx.y;
    int lane = threadIdx.x & 31, w = threadIdx.x >> 5;
    int wm = w & 1, wn = w >> 1;
    bool full = d_use[t * 64 + am] != 0;
    const unsigned* Ahi_r = d_Ahi[rb];
    const unsigned* Alo_r = d_Alo[rb];
    unsigned* Ahi_w = d_Ahi[rb ^ 1];
    unsigned* Alo_w = d_Alo[rb ^ 1];

    float acc[4][6][4];
#pragma unroll
    for (int i = 0; i < 4; i++)
#pragma unroll
        for (int j = 0; j < 6; j++)
#pragma unroll
            for (int q = 0; q < 4; q++) acc[i][j][q] = 0.f;

    int mtb = am * 8 + wm * 4;
    int ntb = cg * 4 + wn;   // n-tile for chunk j: j*32 + ntb

#pragma unroll 1
    for (int kt = 0; kt < 16; kt++) {
        uint4 ah[4], al[4];
#pragma unroll
        for (int i = 0; i < 4; i++) {
            int base = (((mtb + i) * 16 + kt) * 32 + lane) * 4;
            ah[i] = *(const uint4*)(Ahi_r + base);
            al[i] = *(const uint4*)(Alo_r + base);
        }
#pragma unroll
        for (int j = 0; j < 3; j++) {
            int bb = ((j * 32 + ntb) * 16 + kt) * 32 + lane;
            uint2 Bh = d_WGhi[bb], Bl = d_WGlo[bb];
#pragma unroll
            for (int i = 0; i < 4; i++) {
                mma16816(acc[i][j], ah[i], Bh);
                mma16816(acc[i][j], al[i], Bh);
                mma16816(acc[i][j], ah[i], Bl);
            }
        }
        if (full) {
#pragma unroll
            for (int j = 3; j < 6; j++) {
                int bb = ((j * 32 + ntb) * 16 + kt) * 32 + lane;
                uint2 Bh = d_WGhi[bb], Bl = d_WGlo[bb];
#pragma unroll
                for (int i = 0; i < 4; i++) {
                    mma16816(acc[i][j], ah[i], Bh);
                    mma16816(acc[i][j], al[i], Bh);
                    mma16816(acc[i][j], ah[i], Bl);
                }
            }
        }
    }

    // ---- gate epilogue ----
    int lane4 = lane >> 2;
    int c = cg * 32 + wn * 8 + (lane & 3) * 2;  // global hidden col (even)
    float Bh0[3], Bh1[3];
#pragma unroll
    for (int g = 0; g < 3; g++) { Bh0[g] = bh[g*256 + c]; Bh1[g] = bh[g*256 + c + 1]; }
    float Bi0[3], Bi1[3], M0a[3], M0b[3], M1a[3], M1b[3], C0[3], C1[3];
    if (full) {
#pragma unroll
        for (int g = 0; g < 3; g++) { Bi0[g] = bi[g*256 + c]; Bi1[g] = bi[g*256 + c + 1]; }
    } else {
#pragma unroll
        for (int g = 0; g < 3; g++) {
            int n0 = g*256 + c;
            M0a[g] = d_Mi[2*n0];     M0b[g] = d_Mi[2*n0 + 1];     C0[g] = d_ci[n0];
            M1a[g] = d_Mi[2*n0 + 2]; M1b[g] = d_Mi[2*n0 + 3];     C1[g] = d_ci[n0 + 1];
        }
    }
    int base_r = am * 128 + wm * 64 + lane4;

#pragma unroll
    for (int i = 0; i < 4; i++) {
#pragma unroll
        for (int half = 0; half < 2; half++) {
            int r = base_r + i * 16 + half * 8;
            int q0 = half * 2;
            float2 ho = *(const float2*)(d_h + r * 256 + c);
            float hr0 = acc[i][0][q0] + Bh0[0], hr1 = acc[i][0][q0+1] + Bh1[0];
            float hz0 = acc[i][1][q0] + Bh0[1], hz1 = acc[i][1][q0+1] + Bh1[1];
            float hn0 = acc[i][2][q0] + Bh0[2], hn1 = acc[i][2][q0+1] + Bh1[2];
            float ir0, iz0, in0g, ir1, iz1, in1g;
            if (full) {
                ir0  = acc[i][3][q0] + Bi0[0];  ir1  = acc[i][3][q0+1] + Bi1[0];
                iz0  = acc[i][4][q0] + Bi0[1];  iz1  = acc[i][4][q0+1] + Bi1[1];
                in0g = acc[i][5][q0] + Bi0[2];  in1g = acc[i][5][q0+1] + Bi1[2];
            } else {
                int b = r & 127;
                const float* ip = inp + ((b * 64 + am) * 20 + t) * 2;
                float x0 = ip[0], x1 = ip[1];
                ir0  = x0 * M0a[0] + x1 * M0b[0] + C0[0];
                iz0  = x0 * M0a[1] + x1 * M0b[1] + C0[1];
                in0g = x0 * M0a[2] + x1 * M0b[2] + C0[2];
                ir1  = x0 * M1a[0] + x1 * M1b[0] + C1[0];
                iz1  = x0 * M1a[1] + x1 * M1b[1] + C1[1];
                in1g = x0 * M1a[2] + x1 * M1b[2] + C1[2];
            }
            float rg0 = sigf(ir0 + hr0), zg0 = sigf(iz0 + hz0);
            float ng0 = tanh_f(in0g + rg0 * hn0);
            float h0 = (1.f - zg0) * ng0 + zg0 * ho.x;
            float rg1 = sigf(ir1 + hr1), zg1 = sigf(iz1 + hz1);
            float ng1 = tanh_f(in1g + rg1 * hn1);
            float h1 = (1.f - zg1) * ng1 + zg1 * ho.y;
            *(float2*)(d_h + r * 256 + c) = make_float2(h0, h1);
            unsigned lo, hi = packsplit(h0, h1, lo);
            int widx = fidx(r, c, 16);
            Ahi_w[widx] = hi; Alo_w[widx] = lo;
        }
    }
}

// ---- fused FC head: fc1 (mma) -> smem frags -> fc2 (mma) -> smem -> fc3 + mask ----
extern __shared__ unsigned smem_u[];
__global__ void __launch_bounds__(256) k_fc(const float* __restrict__ b1,
                                            const float* __restrict__ b2,
                                            const float* __restrict__ w3,
                                            const float* __restrict__ b3,
                                            const float* __restrict__ inp,
                                            float* __restrict__ out, int t, int rb) {
    unsigned* sY1hi = smem_u;
    unsigned* sY1lo = smem_u + 8192;
    float* sy2 = (float*)smem_u;          // reused after sync (stride 132)
    const unsigned* Ahi_r = d_Ahi[rb];
    const unsigned* Alo_r = d_Alo[rb];

    int lane = threadIdx.x & 31, w = threadIdx.x >> 5;
    int wm = w & 1, wn = w >> 1;
    int lane4 = lane >> 2;

    // ---- fc1 ----
    float acc[4][4][4];
#pragma unroll
    for (int i = 0; i < 4; i++)
#pragma unroll
        for (int j = 0; j < 4; j++)
#pragma unroll
            for (int q = 0; q < 4; q++) acc[i][j][q] = 0.f;
    int mtb = blockIdx.x * 8 + wm * 4;
#pragma unroll 1
    for (int kt = 0; kt < 16; kt++) {
        uint4 ah[4], al[4];
#pragma unroll
        for (int i = 0; i < 4; i++) {
            int base = (((mtb + i) * 16 + kt) * 32 + lane) * 4;
            ah[i] = *(const uint4*)(Ahi_r + base);
            al[i] = *(const uint4*)(Alo_r + base);
        }
#pragma unroll
        for (int j = 0; j < 4; j++) {
            int bb = ((wn * 4 + j) * 16 + kt) * 32 + lane;
            uint2 Bh = d_W1hi[bb], Bl = d_W1lo[bb];
#pragma unroll
            for (int i = 0; i < 4; i++) {
                mma16816(acc[i][j], ah[i], Bh);
                mma16816(acc[i][j], al[i], Bh);
                mma16816(acc[i][j], ah[i], Bl);
            }
        }
    }
#pragma unroll
    for (int i = 0; i < 4; i++)
#pragma unroll
        for (int j = 0; j < 4; j++) {
            int rr = wm * 64 + i * 16 + lane4;
            int cc = wn * 32 + j * 8 + (lane & 3) * 2;
            float bb0 = b1[cc], bb1 = b1[cc + 1];
            float v0 = eluf(acc[i][j][0] + bb0);
            float v1 = eluf(acc[i][j][1] + bb1);
            unsigned lo, hi = packsplit(v0, v1, lo);
            int widx = fidx(rr, cc, 8);
            sY1hi[widx] = hi; sY1lo[widx] = lo;
            v0 = eluf(acc[i][j][2] + bb0);
            v1 = eluf(acc[i][j][3] + bb1);
            hi = packsplit(v0, v1, lo);
            widx = fidx(rr + 8, cc, 8);
            sY1hi[widx] = hi; sY1lo[widx] = lo;
        }
    __syncthreads();

    // ---- fc2 ----
    float acc2[4][4][4];
#pragma unroll
    for (int i = 0; i < 4; i++)
#pragma unroll
        for (int j = 0; j < 4; j++)
#pragma unroll
            for (int q = 0; q < 4; q++) acc2[i][j][q] = 0.f;
#pragma unroll 1
    for (int kt = 0; kt < 8; kt++) {
        uint4 ah[4], al[4];
#pragma unroll
        for (int i = 0; i < 4; i++) {
            int base = (((wm * 4 + i) * 8 + kt) * 32 + lane) * 4;
            ah[i] = *(const uint4*)(sY1hi + base);
            al[i] = *(const uint4*)(sY1lo + base);
        }
#pragma unroll
        for (int j = 0; j < 4; j++) {
            int bb = ((wn * 4 + j) * 8 + kt) * 32 + lane;
            uint2 Bh = d_W2hi[bb], Bl = d_W2lo[bb];
#pragma unroll
            for (int i = 0; i < 4; i++) {
                mma16816(acc2[i][j], ah[i], Bh);
                mma16816(acc2[i][j], al[i], Bh);
                mma16816(acc2[i][j], ah[i], Bl);
            }
        }
    }
    __syncthreads();   // all sY1 reads done before overwrite with y2

#pragma unroll
    for (int i = 0; i < 4; i++)
#pragma unroll
        for (int j = 0; j < 4; j++) {
            int rr = wm * 64 + i * 16 + lane4;
            int cc = wn * 32 + j * 8 + (lane & 3) * 2;
            float bb0 = b2[cc], bb1 = b2[cc + 1];
            sy2[rr * 132 + cc]           = eluf(acc2[i][j][0] + bb0);
            sy2[rr * 132 + cc + 1]       = eluf(acc2[i][j][1] + bb1);
            sy2[(rr + 8) * 132 + cc]     = eluf(acc2[i][j][2] + bb0);
            sy2[(rr + 8) * 132 + cc + 1] = eluf(acc2[i][j][3] + bb1);
        }
    __syncthreads();

    // ---- fc3 + gt mask ----
    int tid = threadIdx.x;
    int rl = tid >> 1, cr = tid & 1;
    const float* wr = w3 + cr * 128;
    float s = b3[cr];
#pragma unroll 8
    for (int k = 0; k < 128; k++) s += sy2[rl * 132 + k] * __ldg(wr + k);
    int a = blockIdx.x, b = rl;
    float gv = inp[((b * 64 + a) * 20 + t) * 2 + cr];
    out[((b * 64 + a) * 12 + (t - 8)) * 2 + cr] = (gv != 0.f) ? s : 0.f;
}

extern "C" void kernel_launch(void* const* d_in, const int* in_sizes, int n_in,
                              void* d_out, int out_size) {
    int sh = (n_in >= 15 && in_sizes[1] <= 4) ? 0 : -1;
    const float* inputs = (const float*)d_in[0];
    const unsigned char* eps = (const unsigned char*)d_in[2 + sh];
    const float* ew = (const float*)d_in[3 + sh];
    const float* eb = (const float*)d_in[4 + sh];
    const float* wi = (const float*)d_in[5 + sh];
    const float* wh = (const float*)d_in[6 + sh];
    const float* bi = (const float*)d_in[7 + sh];
    const float* bh = (const float*)d_in[8 + sh];
    const float* w1 = (const float*)d_in[9 + sh];
    const float* b1 = (const float*)d_in[10 + sh];
    const float* w2 = (const float*)d_in[11 + sh];
    const float* b2 = (const float*)d_in[12 + sh];
    const float* w3 = (const float*)d_in[13 + sh];
    const float* b3 = (const float*)d_in[14 + sh];
    float* out = (float*)d_out;

    cudaFuncSetAttribute(k_fc, cudaFuncAttributeMaxDynamicSharedMemorySize, 69632);

    s_init<<<8192, 256>>>();
    s_detect<<<1, 32>>>(eps);
    s_pack<<<440, 256>>>(wh, wi, w1, w2, ew, eb, bi, eps);

    for (int t = 0; t < 20; t++) {
        k_step<<<dim3(64, 8), 256>>>(inputs, bh, bi, t, t & 1);
        if (t >= 8)
            k_fc<<<64, 256, 69632>>>(b1, b2, w3, b3, inputs, out, t, (t + 1) & 1);
    }
}

// round 4
// speedup vs baseline: 1.6438x; 1.2915x over previous
#include <cuda_runtime.h>
#include <cuda_fp16.h>

#define RD 8192

// ---- static device scratch ----
__device__ float d_h[RD*256];
__device__ unsigned d_Ahi[2][512*16*32*4];   // double-buffered h fragments (hi)
__device__ unsigned d_Alo[2][512*16*32*4];   // (lo)
__device__ uint2 d_WGhi[192*16*32];          // chunks: Wh_r,Wh_z,Wh_n,comb_r,comb_z,Wi_n
__device__ uint2 d_WGlo[192*16*32];
__device__ uint2 d_W1hi[16*16*32];
__device__ uint2 d_W1lo[16*16*32];
__device__ uint2 d_W2hi[16*8*32];
__device__ uint2 d_W2lo[16*8*32];
__device__ float d_Mi[768*2];
__device__ float d_ci[768];
__device__ unsigned char d_use[20*64];
__device__ int d_epsMode;

// ---- helpers ----
__device__ __forceinline__ unsigned packsplit(float v0, float v1, unsigned &lo) {
    __half h0 = __float2half(v0);
    __half h1 = __float2half(v1);
    __half l0 = __float2half(v0 - __half2float(h0));
    __half l1 = __float2half(v1 - __half2float(h1));
    lo = ((unsigned)__half_as_ushort(l1) << 16) | (unsigned)__half_as_ushort(l0);
    return ((unsigned)__half_as_ushort(h1) << 16) | (unsigned)__half_as_ushort(h0);
}
__device__ __forceinline__ int fidx(int r, int c, int KT) {
    return (((r >> 4) * KT + (c >> 4)) * 32 + (r & 7) * 4 + ((c & 7) >> 1)) * 4
           + ((r >> 3) & 1) + (((c >> 3) & 1) << 1);
}
__device__ __forceinline__ void mma16816(float (&c)[4], const uint4 a, const uint2 b) {
    asm volatile(
        "mma.sync.aligned.m16n8k16.row.col.f32.f16.f16.f32 "
        "{%0,%1,%2,%3},{%4,%5,%6,%7},{%8,%9},{%0,%1,%2,%3};\n"
        : "+f"(c[0]), "+f"(c[1]), "+f"(c[2]), "+f"(c[3])
        : "r"(a.x), "r"(a.y), "r"(a.z), "r"(a.w), "r"(b.x), "r"(b.y));
}
__device__ __forceinline__ float sigf(float x) {
    return __fdividef(1.f, 1.f + __expf(-x));
}
__device__ __forceinline__ float tanh_f(float x) {
    return 2.f * sigf(2.f * x) - 1.f;
}
__device__ __forceinline__ float eluf(float x) { return x > 0.f ? x : (__expf(x) - 1.f); }

// ---- setup ----
__global__ void s_init() {
    int i = blockIdx.x * 256 + threadIdx.x;
    if (i < RD*256) d_h[i] = 0.f;
    if (i < 512*16*32*4) { d_Ahi[0][i] = 0u; d_Alo[0][i] = 0u; }
}

__global__ void s_detect(const unsigned char* eps) {
    if (threadIdx.x == 0 && blockIdx.x == 0) {
        int ones3f = 0, nz123 = 0;
        for (int i = 0; i < 768; i++) {
            unsigned char b = eps[i];
            if ((i & 3) == 3 && b == 0x3f) ones3f++;
            if ((i & 3) != 0 && b != 0) nz123++;
        }
        d_epsMode = (ones3f > 0) ? 2 : (nz123 == 0 ? 1 : 0);
    }
}

__global__ void s_pack(const float* __restrict__ wh, const float* __restrict__ wi,
                       const float* __restrict__ w1, const float* __restrict__ w2,
                       const float* __restrict__ ew, const float* __restrict__ eb,
                       const float* __restrict__ bi, const unsigned char* __restrict__ eps) {
    int id = blockIdx.x * 256 + threadIdx.x;
    if (id < 98304) {
        // WG chunk layout (6 x 256 output cols):
        //  [0,768): Wh rows (r,z,n)
        //  [768,1280): comb = Wi+Wh rows (r,z)
        //  [1280,1536): Wi rows (n)
        int lane = id & 31, kt = (id >> 5) & 15, nt = id >> 9;
        int n = nt * 8 + (lane >> 2);
        const float* sa;
        const float* sb = 0;
        if (n < 768)        { sa = wh + n * 256; }
        else if (n < 1280)  { sa = wi + (n - 768) * 256; sb = wh + (n - 768) * 256; }
        else                { sa = wi + (n - 1280 + 512) * 256; }
        int k0 = kt * 16 + (lane & 3) * 2;
        float v0 = sa[k0]     + (sb ? sb[k0]     : 0.f);
        float v1 = sa[k0+1]   + (sb ? sb[k0+1]   : 0.f);
        float v2 = sa[k0+8]   + (sb ? sb[k0+8]   : 0.f);
        float v3 = sa[k0+9]   + (sb ? sb[k0+9]   : 0.f);
        uint2 H, L;
        H.x = packsplit(v0, v1, L.x);
        H.y = packsplit(v2, v3, L.y);
        d_WGhi[id] = H; d_WGlo[id] = L;
    } else if (id < 106496) {              // W1: [128,256]
        int j = id - 98304;
        int lane = j & 31, kt = (j >> 5) & 15, nt = j >> 9;
        const float* src = w1 + (nt * 8 + (lane >> 2)) * 256;
        int k0 = kt * 16 + (lane & 3) * 2;
        uint2 H, L;
        H.x = packsplit(src[k0],   src[k0+1], L.x);
        H.y = packsplit(src[k0+8], src[k0+9], L.y);
        d_W1hi[j] = H; d_W1lo[j] = L;
    } else if (id < 110592) {              // W2: [128,128]
        int j = id - 106496;
        int lane = j & 31, kt = (j >> 5) & 7, nt = j >> 8;
        const float* src = w2 + (nt * 8 + (lane >> 2)) * 128;
        int k0 = kt * 16 + (lane & 3) * 2;
        uint2 H, L;
        H.x = packsplit(src[k0],   src[k0+1], L.x);
        H.y = packsplit(src[k0+8], src[k0+9], L.y);
        d_W2hi[j] = H; d_W2lo[j] = L;
    } else if (id < 111360) {              // Mi = Wi@embed_w, ci = Wi@embed_b + bi
        int n = id - 110592;
        const float* wr = wi + n * 256;
        float m0 = 0.f, m1 = 0.f, cc = 0.f;
        for (int k = 0; k < 256; k++) {
            float v = wr[k];
            m0 += v * ew[2*k]; m1 += v * ew[2*k+1]; cc += v * eb[k];
        }
        d_Mi[2*n] = m0; d_Mi[2*n+1] = m1; d_ci[n] = cc + bi[n];
    } else if (id < 112640) {              // d_use[t][a]
        int j = id - 111360;
        int t = j >> 6, a = j & 63;
        unsigned char u = 0;
        if (t >= 8) {
            int m = (t - 8) * 64 + a;
            int mode = d_epsMode;
            float v = (mode == 2) ? ((const float*)eps)[m]
                    : (mode == 1) ? (float)((const int*)eps)[m]
                    : (float)eps[m];
            u = (v != 0.f) ? 1 : 0;
        }
        d_use[j] = u;
    }
}

// ---- fused GRU step: pipelined mma + gates + h update + fragment repack ----
// CTA: (agent, 32-col group, 64-row half). Warp: 2 m-tiles x 1 n-tile x 4 chunks.
__global__ void __launch_bounds__(256, 2) k_step(const float* __restrict__ inp,
                                                 const float* __restrict__ bh,
                                                 const float* __restrict__ bi,
                                                 int t, int rb) {
    int am = blockIdx.x, cg = blockIdx.y, rz = blockIdx.z;
    int lane = threadIdx.x & 31, w = threadIdx.x >> 5;
    int wm = w & 1, wn = w >> 1;           // wn in 0..3
    bool full = d_use[t * 64 + am] != 0;
    const uint4* Ahi_r = (const uint4*)d_Ahi[rb];
    const uint4* Alo_r = (const uint4*)d_Alo[rb];
    unsigned* Ahi_w = d_Ahi[rb ^ 1];
    unsigned* Alo_w = d_Alo[rb ^ 1];

    int ntb = cg * 4 + wn;                 // n-tile within a 256-col chunk
    int chk0, chk1, chk2, chk3;
    if (full) { chk0 = 3; chk1 = 4; chk2 = 2; chk3 = 5; }
    else      { chk0 = 0; chk1 = 1; chk2 = 2; chk3 = 2; }
    // uint2 index base for chunk j at kt: ((chk*32+ntb)*16+kt)*32+lane
    int b0 = ((chk0 * 32 + ntb) * 16) * 32 + lane;
    int b1 = ((chk1 * 32 + ntb) * 16) * 32 + lane;
    int b2 = ((chk2 * 32 + ntb) * 16) * 32 + lane;
    int b3 = ((chk3 * 32 + ntb) * 16) * 32 + lane;

    int gmt0 = am * 8 + rz * 4 + wm * 2;   // global m-tile of acc row-tile 0
    // uint4 index for (mt,kt): (mt*16+kt)*32+lane
    int a0 = (gmt0 * 16) * 32 + lane;
    int a1 = ((gmt0 + 1) * 16) * 32 + lane;

    float acc[2][4][4];
#pragma unroll
    for (int i = 0; i < 2; i++)
#pragma unroll
        for (int j = 0; j < 4; j++)
#pragma unroll
            for (int q = 0; q < 4; q++) acc[i][j][q] = 0.f;

    // prologue: load kt=0
    uint4 ahC0 = Ahi_r[a0], ahC1 = Ahi_r[a1];
    uint4 alC0 = Alo_r[a0], alC1 = Alo_r[a1];
    uint2 bhC0 = d_WGhi[b0], bhC1 = d_WGhi[b1], bhC2 = d_WGhi[b2], bhC3 = d_WGhi[b3];
    uint2 blC0 = d_WGlo[b0], blC1 = d_WGlo[b1], blC2 = d_WGlo[b2], blC3 = d_WGlo[b3];

#pragma unroll 4
    for (int kt = 0; kt < 16; kt++) {
        int ktn = (kt + 1 < 16) ? (kt + 1) : 15;
        int ao = ktn * 32, bo = ktn * 32;
        uint4 ahN0 = Ahi_r[a0 + ao], ahN1 = Ahi_r[a1 + ao];
        uint4 alN0 = Alo_r[a0 + ao], alN1 = Alo_r[a1 + ao];
        uint2 bhN0 = d_WGhi[b0 + bo], bhN1 = d_WGhi[b1 + bo];
        uint2 bhN2 = d_WGhi[b2 + bo], bhN3 = d_WGhi[b3 + bo];
        uint2 blN0 = d_WGlo[b0 + bo], blN1 = d_WGlo[b1 + bo];
        uint2 blN2 = d_WGlo[b2 + bo], blN3 = d_WGlo[b3 + bo];

        mma16816(acc[0][0], ahC0, bhC0); mma16816(acc[1][0], ahC1, bhC0);
        mma16816(acc[0][0], alC0, bhC0); mma16816(acc[1][0], alC1, bhC0);
        mma16816(acc[0][0], ahC0, blC0); mma16816(acc[1][0], ahC1, blC0);
        mma16816(acc[0][1], ahC0, bhC1); mma16816(acc[1][1], ahC1, bhC1);
        mma16816(acc[0][1], alC0, bhC1); mma16816(acc[1][1], alC1, bhC1);
        mma16816(acc[0][1], ahC0, blC1); mma16816(acc[1][1], ahC1, blC1);
        mma16816(acc[0][2], ahC0, bhC2); mma16816(acc[1][2], ahC1, bhC2);
        mma16816(acc[0][2], alC0, bhC2); mma16816(acc[1][2], alC1, bhC2);
        mma16816(acc[0][2], ahC0, blC2); mma16816(acc[1][2], ahC1, blC2);
        if (full) {
            mma16816(acc[0][3], ahC0, bhC3); mma16816(acc[1][3], ahC1, bhC3);
            mma16816(acc[0][3], alC0, bhC3); mma16816(acc[1][3], alC1, bhC3);
            mma16816(acc[0][3], ahC0, blC3); mma16816(acc[1][3], ahC1, blC3);
        }
        ahC0 = ahN0; ahC1 = ahN1; alC0 = alN0; alC1 = alN1;
        bhC0 = bhN0; bhC1 = bhN1; bhC2 = bhN2; bhC3 = bhN3;
        blC0 = blN0; blC1 = blN1; blC2 = blN2; blC3 = blN3;
    }

    // ---- gate epilogue ----
    int lane4 = lane >> 2;
    int c = cg * 32 + wn * 8 + (lane & 3) * 2;   // hidden col (even)
    float bhr0 = bh[c],       bhr1 = bh[c + 1];
    float bhz0 = bh[256 + c], bhz1 = bh[257 + c];
    float bhn0 = bh[512 + c], bhn1 = bh[513 + c];
    float bir0, bir1, biz0, biz1, bin0, bin1;
    float M0a[3], M0b[3], M1a[3], M1b[3], C0[3], C1[3];
    if (full) {
        bir0 = bi[c];       bir1 = bi[c + 1];
        biz0 = bi[256 + c]; biz1 = bi[257 + c];
        bin0 = bi[512 + c]; bin1 = bi[513 + c];
    } else {
#pragma unroll
        for (int g = 0; g < 3; g++) {
            int n0 = g * 256 + c;
            M0a[g] = d_Mi[2*n0];     M0b[g] = d_Mi[2*n0 + 1];   C0[g] = d_ci[n0];
            M1a[g] = d_Mi[2*n0 + 2]; M1b[g] = d_Mi[2*n0 + 3];   C1[g] = d_ci[n0 + 1];
        }
    }

#pragma unroll
    for (int i = 0; i < 2; i++) {
#pragma unroll
        for (int half = 0; half < 2; half++) {
            int r = (gmt0 + i) * 16 + half * 8 + lane4;
            int q0 = half * 2;
            float2 ho = *(const float2*)(d_h + r * 256 + c);
            float r0g, r1g, z0g, z1g, n0g, n1g;
            if (full) {
                r0g = sigf(acc[i][0][q0]   + bir0 + bhr0);
                r1g = sigf(acc[i][0][q0+1] + bir1 + bhr1);
                z0g = sigf(acc[i][1][q0]   + biz0 + bhz0);
                z1g = sigf(acc[i][1][q0+1] + biz1 + bhz1);
                n0g = tanh_f(acc[i][3][q0]   + bin0 + r0g * (acc[i][2][q0]   + bhn0));
                n1g = tanh_f(acc[i][3][q0+1] + bin1 + r1g * (acc[i][2][q0+1] + bhn1));
            } else {
                int b = r & 127;
                const float* ip = inp + ((b * 64 + am) * 20 + t) * 2;
                float x0 = ip[0], x1 = ip[1];
                float ir0 = x0 * M0a[0] + x1 * M0b[0] + C0[0];
                float iz0 = x0 * M0a[1] + x1 * M0b[1] + C0[1];
                float in0 = x0 * M0a[2] + x1 * M0b[2] + C0[2];
                float ir1 = x0 * M1a[0] + x1 * M1b[0] + C1[0];
                float iz1 = x0 * M1a[1] + x1 * M1b[1] + C1[1];
                float in1 = x0 * M1a[2] + x1 * M1b[2] + C1[2];
                r0g = sigf(ir0 + acc[i][0][q0]   + bhr0);
                r1g = sigf(ir1 + acc[i][0][q0+1] + bhr1);
                z0g = sigf(iz0 + acc[i][1][q0]   + bhz0);
                z1g = sigf(iz1 + acc[i][1][q0+1] + bhz1);
                n0g = tanh_f(in0 + r0g * (acc[i][2][q0]   + bhn0));
                n1g = tanh_f(in1 + r1g * (acc[i][2][q0+1] + bhn1));
            }
            float h0 = (1.f - z0g) * n0g + z0g * ho.x;
            float h1 = (1.f - z1g) * n1g + z1g * ho.y;
            *(float2*)(d_h + r * 256 + c) = make_float2(h0, h1);
            unsigned lo, hi = packsplit(h0, h1, lo);
            int widx = fidx(r, c, 16);
            Ahi_w[widx] = hi; Alo_w[widx] = lo;
        }
    }
}

// ---- fused FC head on 64 rows/CTA: fc1 -> smem frags -> fc2 -> smem -> fc3 ----
extern __shared__ unsigned smem_u[];
__global__ void __launch_bounds__(256) k_fc(const float* __restrict__ b1,
                                            const float* __restrict__ b2,
                                            const float* __restrict__ w3,
                                            const float* __restrict__ b3,
                                            const float* __restrict__ inp,
                                            float* __restrict__ out, int t, int rb) {
    unsigned* sY1hi = smem_u;          // 4096 u32
    unsigned* sY1lo = smem_u + 4096;   // 4096 u32
    float* sy2 = (float*)smem_u;       // 64*132 floats, overwrites after sync
    const uint4* Ahi_r = (const uint4*)d_Ahi[rb];
    const uint4* Alo_r = (const uint4*)d_Alo[rb];

    int lane = threadIdx.x & 31, w = threadIdx.x >> 5;
    int wm = w & 1, wn = w >> 1;
    int lane4 = lane >> 2;
    int agent = blockIdx.x >> 1, halfb = blockIdx.x & 1;
    int gmt0 = agent * 8 + halfb * 4 + wm * 2;

    // ---- fc1 ----
    float acc[2][4][4];
#pragma unroll
    for (int i = 0; i < 2; i++)
#pragma unroll
        for (int j = 0; j < 4; j++)
#pragma unroll
            for (int q = 0; q < 4; q++) acc[i][j][q] = 0.f;
#pragma unroll 2
    for (int kt = 0; kt < 16; kt++) {
        uint4 ah[2], al[2];
#pragma unroll
        for (int i = 0; i < 2; i++) {
            int base = ((gmt0 + i) * 16 + kt) * 32 + lane;
            ah[i] = Ahi_r[base];
            al[i] = Alo_r[base];
        }
#pragma unroll
        for (int j = 0; j < 4; j++) {
            int bb = ((wn * 4 + j) * 16 + kt) * 32 + lane;
            uint2 Bh = d_W1hi[bb], Bl = d_W1lo[bb];
#pragma unroll
            for (int i = 0; i < 2; i++) {
                mma16816(acc[i][j], ah[i], Bh);
                mma16816(acc[i][j], al[i], Bh);
                mma16816(acc[i][j], ah[i], Bl);
            }
        }
    }
#pragma unroll
    for (int i = 0; i < 2; i++)
#pragma unroll
        for (int j = 0; j < 4; j++) {
            int rr = wm * 32 + i * 16 + lane4;          // local row
            int cc = wn * 32 + j * 8 + (lane & 3) * 2;
            float bb0 = b1[cc], bb1 = b1[cc + 1];
            float v0 = eluf(acc[i][j][0] + bb0);
            float v1 = eluf(acc[i][j][1] + bb1);
            unsigned lo, hi = packsplit(v0, v1, lo);
            int widx = fidx(rr, cc, 8);
            sY1hi[widx] = hi; sY1lo[widx] = lo;
            v0 = eluf(acc[i][j][2] + bb0);
            v1 = eluf(acc[i][j][3] + bb1);
            hi = packsplit(v0, v1, lo);
            widx = fidx(rr + 8, cc, 8);
            sY1hi[widx] = hi; sY1lo[widx] = lo;
        }
    __syncthreads();

    // ---- fc2 ----
    float acc2[2][4][4];
#pragma unroll
    for (int i = 0; i < 2; i++)
#pragma unroll
        for (int j = 0; j < 4; j++)
#pragma unroll
            for (int q = 0; q < 4; q++) acc2[i][j][q] = 0.f;
    const uint4* sY1hi4 = (const uint4*)sY1hi;
    const uint4* sY1lo4 = (const uint4*)sY1lo;
#pragma unroll 2
    for (int kt = 0; kt < 8; kt++) {
        uint4 ah[2], al[2];
#pragma unroll
        for (int i = 0; i < 2; i++) {
            int base = ((wm * 2 + i) * 8 + kt) * 32 + lane;
            ah[i] = sY1hi4[base];
            al[i] = sY1lo4[base];
        }
#pragma unroll
        for (int j = 0; j < 4; j++) {
            int bb = ((wn * 4 + j) * 8 + kt) * 32 + lane;
            uint2 Bh = d_W2hi[bb], Bl = d_W2lo[bb];
#pragma unroll
            for (int i = 0; i < 2; i++) {
                mma16816(acc2[i][j], ah[i], Bh);
                mma16816(acc2[i][j], al[i], Bh);
                mma16816(acc2[i][j], ah[i], Bl);
            }
        }
    }
    __syncthreads();   // all sY1 reads done before overwrite with y2

#pragma unroll
    for (int i = 0; i < 2; i++)
#pragma unroll
        for (int j = 0; j < 4; j++) {
            int rr = wm * 32 + i * 16 + lane4;
            int cc = wn * 32 + j * 8 + (lane & 3) * 2;
            float bb0 = b2[cc], bb1 = b2[cc + 1];
            sy2[rr * 132 + cc]           = eluf(acc2[i][j][0] + bb0);
            sy2[rr * 132 + cc + 1]       = eluf(acc2[i][j][1] + bb1);
            sy2[(rr + 8) * 132 + cc]     = eluf(acc2[i][j][2] + bb0);
            sy2[(rr + 8) * 132 + cc + 1] = eluf(acc2[i][j][3] + bb1);
        }
    __syncthreads();

    // ---- fc3 + gt mask ----
    int tid = threadIdx.x;
    if (tid < 128) {
        int rl = tid >> 1, cr = tid & 1;
        const float* wr = w3 + cr * 128;
        float s = b3[cr];
#pragma unroll 8
        for (int k = 0; k < 128; k++) s += sy2[rl * 132 + k] * __ldg(wr + k);
        int b = halfb * 64 + rl;
        float gv = inp[((b * 64 + agent) * 20 + t) * 2 + cr];
        out[((b * 64 + agent) * 12 + (t - 8)) * 2 + cr] = (gv != 0.f) ? s : 0.f;
    }
}

extern "C" void kernel_launch(void* const* d_in, const int* in_sizes, int n_in,
                              void* d_out, int out_size) {
    int sh = (n_in >= 15 && in_sizes[1] <= 4) ? 0 : -1;
    const float* inputs = (const float*)d_in[0];
    const unsigned char* eps = (const unsigned char*)d_in[2 + sh];
    const float* ew = (const float*)d_in[3 + sh];
    const float* eb = (const float*)d_in[4 + sh];
    const float* wi = (const float*)d_in[5 + sh];
    const float* wh = (const float*)d_in[6 + sh];
    const float* bi = (const float*)d_in[7 + sh];
    const float* bh = (const float*)d_in[8 + sh];
    const float* w1 = (const float*)d_in[9 + sh];
    const float* b1 = (const float*)d_in[10 + sh];
    const float* w2 = (const float*)d_in[11 + sh];
    const float* b2 = (const float*)d_in[12 + sh];
    const float* w3 = (const float*)d_in[13 + sh];
    const float* b3 = (const float*)d_in[14 + sh];
    float* out = (float*)d_out;

    s_init<<<8192, 256>>>();
    s_detect<<<1, 32>>>(eps);
    s_pack<<<440, 256>>>(wh, wi, w1, w2, ew, eb, bi, eps);

    for (int t = 0; t < 20; t++) {
        k_step<<<dim3(64, 8, 2), 256>>>(inputs, bh, bi, t, t & 1);
        if (t >= 8)
            k_fc<<<128, 256, 34048>>>(b1, b2, w3, b3, inputs, out, t, (t + 1) & 1);
    }
}

// round 5
// speedup vs baseline: 2.2778x; 1.3856x over previous
#include <cuda_runtime.h>
#include <cuda_fp16.h>

#define RD 8192

// ---- static device scratch ----
__device__ unsigned d_Ahi[2][512*16*32*4];   // double-buffered h fragments (hi)
__device__ unsigned d_Alo[2][512*16*32*4];   // (lo)
__device__ uint2 d_WGhi[192*16*32];          // chunks: Wh_r,Wh_z,Wh_n,comb_r,comb_z,Wi_n
__device__ uint2 d_WGlo[192*16*32];
__device__ uint2 d_W1hi[16*16*32];
__device__ uint2 d_W1lo[16*16*32];
__device__ uint2 d_W2hi[16*8*32];
__device__ uint2 d_W2lo[16*8*32];
__device__ float d_Mi[768*2];
__device__ float d_ci[768];
__device__ unsigned char d_use[20*64];
__device__ int d_epsMode;

// ---- helpers ----
__device__ __forceinline__ unsigned packsplit(float v0, float v1, unsigned &lo) {
    __half h0 = __float2half(v0);
    __half h1 = __float2half(v1);
    __half l0 = __float2half(v0 - __half2float(h0));
    __half l1 = __float2half(v1 - __half2float(h1));
    lo = ((unsigned)__half_as_ushort(l1) << 16) | (unsigned)__half_as_ushort(l0);
    return ((unsigned)__half_as_ushort(h1) << 16) | (unsigned)__half_as_ushort(h0);
}
__device__ __forceinline__ int fidx(int r, int c, int KT) {
    return (((r >> 4) * KT + (c >> 4)) * 32 + (r & 7) * 4 + ((c & 7) >> 1)) * 4
           + ((r >> 3) & 1) + (((c >> 3) & 1) << 1);
}
__device__ __forceinline__ void mma16816(float (&c)[4], const uint4 a, const uint2 b) {
    asm volatile(
        "mma.sync.aligned.m16n8k16.row.col.f32.f16.f16.f32 "
        "{%0,%1,%2,%3},{%4,%5,%6,%7},{%8,%9},{%0,%1,%2,%3};\n"
        : "+f"(c[0]), "+f"(c[1]), "+f"(c[2]), "+f"(c[3])
        : "r"(a.x), "r"(a.y), "r"(a.z), "r"(a.w), "r"(b.x), "r"(b.y));
}
__device__ __forceinline__ float sigf(float x) {
    return __fdividef(1.f, 1.f + __expf(-x));
}
__device__ __forceinline__ float tanh_f(float x) {
    return 2.f * sigf(2.f * x) - 1.f;
}
__device__ __forceinline__ float eluf(float x) { return x > 0.f ? x : (__expf(x) - 1.f); }

// ---- setup ----
__global__ void s_init() {
    int i = blockIdx.x * 256 + threadIdx.x;
    if (i < 512*16*32*4) { d_Ahi[0][i] = 0u; d_Alo[0][i] = 0u; }
}

__global__ void s_detect(const unsigned char* eps) {
    if (threadIdx.x == 0 && blockIdx.x == 0) {
        int ones3f = 0, nz123 = 0;
        for (int i = 0; i < 768; i++) {
            unsigned char b = eps[i];
            if ((i & 3) == 3 && b == 0x3f) ones3f++;
            if ((i & 3) != 0 && b != 0) nz123++;
        }
        d_epsMode = (ones3f > 0) ? 2 : (nz123 == 0 ? 1 : 0);
    }
}

__global__ void s_pack(const float* __restrict__ wh, const float* __restrict__ wi,
                       const float* __restrict__ w1, const float* __restrict__ w2,
                       const float* __restrict__ ew, const float* __restrict__ eb,
                       const float* __restrict__ bi, const unsigned char* __restrict__ eps) {
    int id = blockIdx.x * 256 + threadIdx.x;
    if (id < 98304) {
        // WG chunk layout (6 x 256 output cols):
        //  [0,768): Wh rows (r,z,n)
        //  [768,1280): comb = Wi+Wh rows (r,z)
        //  [1280,1536): Wi rows (n)
        int lane = id & 31, kt = (id >> 5) & 15, nt = id >> 9;
        int n = nt * 8 + (lane >> 2);
        const float* sa;
        const float* sb = 0;
        if (n < 768)        { sa = wh + n * 256; }
        else if (n < 1280)  { sa = wi + (n - 768) * 256; sb = wh + (n - 768) * 256; }
        else                { sa = wi + (n - 1280 + 512) * 256; }
        int k0 = kt * 16 + (lane & 3) * 2;
        float v0 = sa[k0]     + (sb ? sb[k0]     : 0.f);
        float v1 = sa[k0+1]   + (sb ? sb[k0+1]   : 0.f);
        float v2 = sa[k0+8]   + (sb ? sb[k0+8]   : 0.f);
        float v3 = sa[k0+9]   + (sb ? sb[k0+9]   : 0.f);
        uint2 H, L;
        H.x = packsplit(v0, v1, L.x);
        H.y = packsplit(v2, v3, L.y);
        d_WGhi[id] = H; d_WGlo[id] = L;
    } else if (id < 106496) {              // W1: [128,256]
        int j = id - 98304;
        int lane = j & 31, kt = (j >> 5) & 15, nt = j >> 9;
        const float* src = w1 + (nt * 8 + (lane >> 2)) * 256;
        int k0 = kt * 16 + (lane & 3) * 2;
        uint2 H, L;
        H.x = packsplit(src[k0],   src[k0+1], L.x);
        H.y = packsplit(src[k0+8], src[k0+9], L.y);
        d_W1hi[j] = H; d_W1lo[j] = L;
    } else if (id < 110592) {              // W2: [128,128]
        int j = id - 106496;
        int lane = j & 31, kt = (j >> 5) & 7, nt = j >> 8;
        const float* src = w2 + (nt * 8 + (lane >> 2)) * 128;
        int k0 = kt * 16 + (lane & 3) * 2;
        uint2 H, L;
        H.x = packsplit(src[k0],   src[k0+1], L.x);
        H.y = packsplit(src[k0+8], src[k0+9], L.y);
        d_W2hi[j] = H; d_W2lo[j] = L;
    } else if (id < 111360) {              // Mi = Wi@embed_w, ci = Wi@embed_b + bi
        int n = id - 110592;
        const float* wr = wi + n * 256;
        float m0 = 0.f, m1 = 0.f, cc = 0.f;
        for (int k = 0; k < 256; k++) {
            float v = wr[k];
            m0 += v * ew[2*k]; m1 += v * ew[2*k+1]; cc += v * eb[k];
        }
        d_Mi[2*n] = m0; d_Mi[2*n+1] = m1; d_ci[n] = cc + bi[n];
    } else if (id < 112640) {              // d_use[t][a]
        int j = id - 111360;
        int t = j >> 6, a = j & 63;
        unsigned char u = 0;
        if (t >= 8) {
            int m = (t - 8) * 64 + a;
            int mode = d_epsMode;
            float v = (mode == 2) ? ((const float*)eps)[m]
                    : (mode == 1) ? (float)((const int*)eps)[m]
                    : (float)eps[m];
            u = (v != 0.f) ? 1 : 0;
        }
        d_use[j] = u;
    }
}

// ---- fused GRU step: pipelined mma + gates + h update + fragment repack ----
// r/z gate chunks use 2-term fp16 split (weight-lo dropped; sigmoid attenuates);
// n gate chunks keep full 3-term. h lives only in the fragment buffers (hi+lo).
__global__ void __launch_bounds__(256, 2) k_step(const float* __restrict__ inp,
                                                 const float* __restrict__ bh,
                                                 const float* __restrict__ bi,
                                                 int t, int rb) {
    int am = blockIdx.x, cg = blockIdx.y, rz = blockIdx.z;
    int lane = threadIdx.x & 31, w = threadIdx.x >> 5;
    int wm = w & 1, wn = w >> 1;           // wn in 0..3
    bool full = d_use[t * 64 + am] != 0;
    const uint4* Ahi_r = (const uint4*)d_Ahi[rb];
    const uint4* Alo_r = (const uint4*)d_Alo[rb];
    unsigned* Ahi_w = d_Ahi[rb ^ 1];
    unsigned* Alo_w = d_Alo[rb ^ 1];

    int ntb = cg * 4 + wn;                 // n-tile within a 256-col chunk
    int chk0, chk1;
    if (full) { chk0 = 3; chk1 = 4; }      // comb_r, comb_z
    else      { chk0 = 0; chk1 = 1; }      // Wh_r, Wh_z
    int b0 = ((chk0 * 32 + ntb) * 16) * 32 + lane;
    int b1 = ((chk1 * 32 + ntb) * 16) * 32 + lane;
    int b2 = ((2    * 32 + ntb) * 16) * 32 + lane;   // Wh_n
    int b3 = ((5    * 32 + ntb) * 16) * 32 + lane;   // Wi_n

    int gmt0 = am * 8 + rz * 4 + wm * 2;
    int a0 = (gmt0 * 16) * 32 + lane;
    int a1 = ((gmt0 + 1) * 16) * 32 + lane;

    float acc[2][4][4];
#pragma unroll
    for (int i = 0; i < 2; i++)
#pragma unroll
        for (int j = 0; j < 4; j++)
#pragma unroll
            for (int q = 0; q < 4; q++) acc[i][j][q] = 0.f;

    // prologue: load kt=0
    uint4 ahC0 = Ahi_r[a0], ahC1 = Ahi_r[a1];
    uint4 alC0 = Alo_r[a0], alC1 = Alo_r[a1];
    uint2 bhC0 = d_WGhi[b0], bhC1 = d_WGhi[b1], bhC2 = d_WGhi[b2];
    uint2 blC2 = d_WGlo[b2];
    uint2 bhC3 = make_uint2(0,0), blC3 = make_uint2(0,0);
    if (full) { bhC3 = d_WGhi[b3]; blC3 = d_WGlo[b3]; }

#pragma unroll 4
    for (int kt = 0; kt < 16; kt++) {
        int ktn = (kt + 1 < 16) ? (kt + 1) : 15;
        int o = ktn * 32;
        uint4 ahN0 = Ahi_r[a0 + o], ahN1 = Ahi_r[a1 + o];
        uint4 alN0 = Alo_r[a0 + o], alN1 = Alo_r[a1 + o];
        uint2 bhN0 = d_WGhi[b0 + o], bhN1 = d_WGhi[b1 + o], bhN2 = d_WGhi[b2 + o];
        uint2 blN2 = d_WGlo[b2 + o];
        uint2 bhN3, blN3;
        if (full) { bhN3 = d_WGhi[b3 + o]; blN3 = d_WGlo[b3 + o]; }

        mma16816(acc[0][0], ahC0, bhC0); mma16816(acc[1][0], ahC1, bhC0);
        mma16816(acc[0][1], ahC0, bhC1); mma16816(acc[1][1], ahC1, bhC1);
        mma16816(acc[0][2], ahC0, bhC2); mma16816(acc[1][2], ahC1, bhC2);
        mma16816(acc[0][0], alC0, bhC0); mma16816(acc[1][0], alC1, bhC0);
        mma16816(acc[0][1], alC0, bhC1); mma16816(acc[1][1], alC1, bhC1);
        mma16816(acc[0][2], alC0, bhC2); mma16816(acc[1][2], alC1, bhC2);
        mma16816(acc[0][2], ahC0, blC2); mma16816(acc[1][2], ahC1, blC2);
        if (full) {
            mma16816(acc[0][3], ahC0, bhC3); mma16816(acc[1][3], ahC1, bhC3);
            mma16816(acc[0][3], alC0, bhC3); mma16816(acc[1][3], alC1, bhC3);
            mma16816(acc[0][3], ahC0, blC3); mma16816(acc[1][3], ahC1, blC3);
            bhC3 = bhN3; blC3 = blN3;
        }
        ahC0 = ahN0; ahC1 = ahN1; alC0 = alN0; alC1 = alN1;
        bhC0 = bhN0; bhC1 = bhN1; bhC2 = bhN2; blC2 = blN2;
    }

    // ---- gate epilogue (h_old reconstructed from fragments: hi+lo) ----
    int lane4 = lane >> 2;
    int c = cg * 32 + wn * 8 + (lane & 3) * 2;   // hidden col (even)
    float bhr0 = bh[c],       bhr1 = bh[c + 1];
    float bhz0 = bh[256 + c], bhz1 = bh[257 + c];
    float bhn0 = bh[512 + c], bhn1 = bh[513 + c];
    float bir0, bir1, biz0, biz1, bin0, bin1;
    float M0a[3], M0b[3], M1a[3], M1b[3], C0[3], C1[3];
    if (full) {
        bir0 = bi[c];       bir1 = bi[c + 1];
        biz0 = bi[256 + c]; biz1 = bi[257 + c];
        bin0 = bi[512 + c]; bin1 = bi[513 + c];
    } else {
#pragma unroll
        for (int g = 0; g < 3; g++) {
            int n0 = g * 256 + c;
            M0a[g] = d_Mi[2*n0];     M0b[g] = d_Mi[2*n0 + 1];   C0[g] = d_ci[n0];
            M1a[g] = d_Mi[2*n0 + 2]; M1b[g] = d_Mi[2*n0 + 3];   C1[g] = d_ci[n0 + 1];
        }
    }
    const unsigned* AhiU = (const unsigned*)Ahi_r;
    const unsigned* AloU = (const unsigned*)Alo_r;

#pragma unroll
    for (int i = 0; i < 2; i++) {
#pragma unroll
        for (int half = 0; half < 2; half++) {
            int r = (gmt0 + i) * 16 + half * 8 + lane4;
            int q0 = half * 2;
            int widx = fidx(r, c, 16);
            unsigned uh = AhiU[widx], ul = AloU[widx];
            __half2 hh = *(__half2*)&uh, hl = *(__half2*)&ul;
            float hox = __half2float(__low2half(hh))  + __half2float(__low2half(hl));
            float hoy = __half2float(__high2half(hh)) + __half2float(__high2half(hl));
            float r0g, r1g, z0g, z1g, n0g, n1g;
            if (full) {
                r0g = sigf(acc[i][0][q0]   + bir0 + bhr0);
                r1g = sigf(acc[i][0][q0+1] + bir1 + bhr1);
                z0g = sigf(acc[i][1][q0]   + biz0 + bhz0);
                z1g = sigf(acc[i][1][q0+1] + biz1 + bhz1);
                n0g = tanh_f(acc[i][3][q0]   + bin0 + r0g * (acc[i][2][q0]   + bhn0));
                n1g = tanh_f(acc[i][3][q0+1] + bin1 + r1g * (acc[i][2][q0+1] + bhn1));
            } else {
                int b = r & 127;
                const float* ip = inp + ((b * 64 + am) * 20 + t) * 2;
                float x0 = ip[0], x1 = ip[1];
                float ir0 = x0 * M0a[0] + x1 * M0b[0] + C0[0];
                float iz0 = x0 * M0a[1] + x1 * M0b[1] + C0[1];
                float in0 = x0 * M0a[2] + x1 * M0b[2] + C0[2];
                float ir1 = x0 * M1a[0] + x1 * M1b[0] + C1[0];
                float iz1 = x0 * M1a[1] + x1 * M1b[1] + C1[1];
                float in1 = x0 * M1a[2] + x1 * M1b[2] + C1[2];
                r0g = sigf(ir0 + acc[i][0][q0]   + bhr0);
                r1g = sigf(ir1 + acc[i][0][q0+1] + bhr1);
                z0g = sigf(iz0 + acc[i][1][q0]   + bhz0);
                z1g = sigf(iz1 + acc[i][1][q0+1] + bhz1);
                n0g = tanh_f(in0 + r0g * (acc[i][2][q0]   + bhn0));
                n1g = tanh_f(in1 + r1g * (acc[i][2][q0+1] + bhn1));
            }
            float h0 = (1.f - z0g) * n0g + z0g * hox;
            float h1 = (1.f - z1g) * n1g + z1g * hoy;
            unsigned lo, hi = packsplit(h0, h1, lo);
            Ahi_w[widx] = hi; Alo_w[widx] = lo;
        }
    }
}

// ---- fused FC head on 64 rows/CTA: fc1 -> smem frags -> fc2 -> smem -> fc3 ----
extern __shared__ unsigned smem_u[];
__global__ void __launch_bounds__(256) k_fc(const float* __restrict__ b1,
                                            const float* __restrict__ b2,
                                            const float* __restrict__ w3,
                                            const float* __restrict__ b3,
                                            const float* __restrict__ inp,
                                            float* __restrict__ out, int t, int rb) {
    unsigned* sY1hi = smem_u;          // 4096 u32
    unsigned* sY1lo = smem_u + 4096;   // 4096 u32
    float* sy2 = (float*)smem_u;       // 64*132 floats, overwrites after sync
    const uint4* Ahi_r = (const uint4*)d_Ahi[rb];
    const uint4* Alo_r = (const uint4*)d_Alo[rb];

    int lane = threadIdx.x & 31, w = threadIdx.x >> 5;
    int wm = w & 1, wn = w >> 1;
    int lane4 = lane >> 2;
    int agent = blockIdx.x >> 1, halfb = blockIdx.x & 1;
    int gmt0 = agent * 8 + halfb * 4 + wm * 2;

    // ---- fc1 ----
    float acc[2][4][4];
#pragma unroll
    for (int i = 0; i < 2; i++)
#pragma unroll
        for (int j = 0; j < 4; j++)
#pragma unroll
            for (int q = 0; q < 4; q++) acc[i][j][q] = 0.f;
#pragma unroll 2
    for (int kt = 0; kt < 16; kt++) {
        uint4 ah[2], al[2];
#pragma unroll
        for (int i = 0; i < 2; i++) {
            int base = ((gmt0 + i) * 16 + kt) * 32 + lane;
            ah[i] = Ahi_r[base];
            al[i] = Alo_r[base];
        }
#pragma unroll
        for (int j = 0; j < 4; j++) {
            int bb = ((wn * 4 + j) * 16 + kt) * 32 + lane;
            uint2 Bh = d_W1hi[bb], Bl = d_W1lo[bb];
#pragma unroll
            for (int i = 0; i < 2; i++) {
                mma16816(acc[i][j], ah[i], Bh);
                mma16816(acc[i][j], al[i], Bh);
                mma16816(acc[i][j], ah[i], Bl);
            }
        }
    }
#pragma unroll
    for (int i = 0; i < 2; i++)
#pragma unroll
        for (int j = 0; j < 4; j++) {
            int rr = wm * 32 + i * 16 + lane4;          // local row
            int cc = wn * 32 + j * 8 + (lane & 3) * 2;
            float bb0 = b1[cc], bb1 = b1[cc + 1];
            float v0 = eluf(acc[i][j][0] + bb0);
            float v1 = eluf(acc[i][j][1] + bb1);
            unsigned lo, hi = packsplit(v0, v1, lo);
            int widx = fidx(rr, cc, 8);
            sY1hi[widx] = hi; sY1lo[widx] = lo;
            v0 = eluf(acc[i][j][2] + bb0);
            v1 = eluf(acc[i][j][3] + bb1);
            hi = packsplit(v0, v1, lo);
            widx = fidx(rr + 8, cc, 8);
            sY1hi[widx] = hi; sY1lo[widx] = lo;
        }
    __syncthreads();

    // ---- fc2 ----
    float acc2[2][4][4];
#pragma unroll
    for (int i = 0; i < 2; i++)
#pragma unroll
        for (int j = 0; j < 4; j++)
#pragma unroll
            for (int q = 0; q < 4; q++) acc2[i][j][q] = 0.f;
    const uint4* sY1hi4 = (const uint4*)sY1hi;
    const uint4* sY1lo4 = (const uint4*)sY1lo;
#pragma unroll 2
    for (int kt = 0; kt < 8; kt++) {
        uint4 ah[2], al[2];
#pragma unroll
        for (int i = 0; i < 2; i++) {
            int base = ((wm * 2 + i) * 8 + kt) * 32 + lane;
            ah[i] = sY1hi4[base];
            al[i] = sY1lo4[base];
        }
#pragma unroll
        for (int j = 0; j < 4; j++) {
            int bb = ((wn * 4 + j) * 8 + kt) * 32 + lane;
            uint2 Bh = d_W2hi[bb], Bl = d_W2lo[bb];
#pragma unroll
            for (int i = 0; i < 2; i++) {
                mma16816(acc2[i][j], ah[i], Bh);
                mma16816(acc2[i][j], al[i], Bh);
                mma16816(acc2[i][j], ah[i], Bl);
            }
        }
    }
    __syncthreads();   // all sY1 reads done before overwrite with y2

#pragma unroll
    for (int i = 0; i < 2; i++)
#pragma unroll
        for (int j = 0; j < 4; j++) {
            int rr = wm * 32 + i * 16 + lane4;
            int cc = wn * 32 + j * 8 + (lane & 3) * 2;
            float bb0 = b2[cc], bb1 = b2[cc + 1];
            sy2[rr * 132 + cc]           = eluf(acc2[i][j][0] + bb0);
            sy2[rr * 132 + cc + 1]       = eluf(acc2[i][j][1] + bb1);
            sy2[(rr + 8) * 132 + cc]     = eluf(acc2[i][j][2] + bb0);
            sy2[(rr + 8) * 132 + cc + 1] = eluf(acc2[i][j][3] + bb1);
        }
    __syncthreads();

    // ---- fc3 + gt mask ----
    int tid = threadIdx.x;
    if (tid < 128) {
        int rl = tid >> 1, cr = tid & 1;
        const float* wr = w3 + cr * 128;
        float s = b3[cr];
#pragma unroll 8
        for (int k = 0; k < 128; k++) s += sy2[rl * 132 + k] * __ldg(wr + k);
        int b = halfb * 64 + rl;
        float gv = inp[((b * 64 + agent) * 20 + t) * 2 + cr];
        out[((b * 64 + agent) * 12 + (t - 8)) * 2 + cr] = (gv != 0.f) ? s : 0.f;
    }
}

extern "C" void kernel_launch(void* const* d_in, const int* in_sizes, int n_in,
                              void* d_out, int out_size) {
    int sh = (n_in >= 15 && in_sizes[1] <= 4) ? 0 : -1;
    const float* inputs = (const float*)d_in[0];
    const unsigned char* eps = (const unsigned char*)d_in[2 + sh];
    const float* ew = (const float*)d_in[3 + sh];
    const float* eb = (const float*)d_in[4 + sh];
    const float* wi = (const float*)d_in[5 + sh];
    const float* wh = (const float*)d_in[6 + sh];
    const float* bi = (const float*)d_in[7 + sh];
    const float* bh = (const float*)d_in[8 + sh];
    const float* w1 = (const float*)d_in[9 + sh];
    const float* b1 = (const float*)d_in[10 + sh];
    const float* w2 = (const float*)d_in[11 + sh];
    const float* b2 = (const float*)d_in[12 + sh];
    const float* w3 = (const float*)d_in[13 + sh];
    const float* b3 = (const float*)d_in[14 + sh];
    float* out = (float*)d_out;

    // side stream + events for overlapping the FC head with the recurrence
    static cudaStream_t s2 = 0;
    static cudaEvent_t evS = 0, evFc[2] = {0, 0};
    if (!s2) {
        cudaStreamCreateWithFlags(&s2, cudaStreamNonBlocking);
        cudaEventCreateWithFlags(&evS, cudaEventDisableTiming);
        cudaEventCreateWithFlags(&evFc[0], cudaEventDisableTiming);
        cudaEventCreateWithFlags(&evFc[1], cudaEventDisableTiming);
    }

    s_init<<<4096, 256>>>();
    s_detect<<<1, 32>>>(eps);
    s_pack<<<440, 256>>>(wh, wi, w1, w2, ew, eb, bi, eps);

    for (int t = 0; t < 20; t++) {
        // k_step(t) overwrites the buffer k_fc(t-2) reads: enforce ordering
        if (t >= 10) cudaStreamWaitEvent((cudaStream_t)0, evFc[t & 1], 0);
        k_step<<<dim3(64, 8, 2), 256>>>(inputs, bh, bi, t, t & 1);
        if (t >= 8) {
            cudaEventRecord(evS, (cudaStream_t)0);
            cudaStreamWaitEvent(s2, evS, 0);
            k_fc<<<128, 256, 34048, s2>>>(b1, b2, w3, b3, inputs, out, t, (t + 1) & 1);
            cudaEventRecord(evFc[t & 1], s2);
        }
    }
    // join the side stream back before capture/launch ends
    cudaStreamWaitEvent((cudaStream_t)0, evFc[0], 0);
    cudaStreamWaitEvent((cudaStream_t)0, evFc[1], 0);
}

// round 6
// speedup vs baseline: 2.6450x; 1.1612x over previous
#include <cuda_runtime.h>
#include <cuda_fp16.h>

#define RD 8192

// ---- static device scratch ----
__device__ unsigned d_Ahi[2][512*16*32*4];   // double-buffered h fragments (hi)
__device__ unsigned d_Alo[2][512*16*32*4];   // (lo)
__device__ uint2 d_WGhi[192*16*32];          // chunks: Wh_r,Wh_z,Wh_n,comb_r,comb_z,Wi_n
__device__ uint2 d_WGlo[192*16*32];
__device__ uint2 d_W1hi[16*16*32];
__device__ uint2 d_W1lo[16*16*32];
__device__ uint2 d_W2hi[16*8*32];
__device__ uint2 d_W2lo[16*8*32];
__device__ float d_Mi[768*2];
__device__ float d_ci[768];
__device__ unsigned char d_use[20*64];
__device__ int d_epsMode;

// ---- helpers ----
__device__ __forceinline__ unsigned packsplit(float v0, float v1, unsigned &lo) {
    __half h0 = __float2half(v0);
    __half h1 = __float2half(v1);
    __half l0 = __float2half(v0 - __half2float(h0));
    __half l1 = __float2half(v1 - __half2float(h1));
    lo = ((unsigned)__half_as_ushort(l1) << 16) | (unsigned)__half_as_ushort(l0);
    return ((unsigned)__half_as_ushort(h1) << 16) | (unsigned)__half_as_ushort(h0);
}
__device__ __forceinline__ int fidx(int r, int c, int KT) {
    return (((r >> 4) * KT + (c >> 4)) * 32 + (r & 7) * 4 + ((c & 7) >> 1)) * 4
           + ((r >> 3) & 1) + (((c >> 3) & 1) << 1);
}
__device__ __forceinline__ void mma16816(float (&c)[4], const uint4 a, const uint2 b) {
    asm volatile(
        "mma.sync.aligned.m16n8k16.row.col.f32.f16.f16.f32 "
        "{%0,%1,%2,%3},{%4,%5,%6,%7},{%8,%9},{%0,%1,%2,%3};\n"
        : "+f"(c[0]), "+f"(c[1]), "+f"(c[2]), "+f"(c[3])
        : "r"(a.x), "r"(a.y), "r"(a.z), "r"(a.w), "r"(b.x), "r"(b.y));
}
__device__ __forceinline__ float sigf(float x) {
    return __fdividef(1.f, 1.f + __expf(-x));
}
__device__ __forceinline__ float tanh_f(float x) {
    return 2.f * sigf(2.f * x) - 1.f;
}
__device__ __forceinline__ float eluf(float x) { return x > 0.f ? x : (__expf(x) - 1.f); }

// ---- setup ----
__global__ void s_init() {
    int i = blockIdx.x * 256 + threadIdx.x;
    if (i < 512*16*32*4) { d_Ahi[0][i] = 0u; d_Alo[0][i] = 0u; }
}

__global__ void s_detect(const unsigned char* eps) {
    if (threadIdx.x == 0 && blockIdx.x == 0) {
        int ones3f = 0, nz123 = 0;
        for (int i = 0; i < 768; i++) {
            unsigned char b = eps[i];
            if ((i & 3) == 3 && b == 0x3f) ones3f++;
            if ((i & 3) != 0 && b != 0) nz123++;
        }
        d_epsMode = (ones3f > 0) ? 2 : (nz123 == 0 ? 1 : 0);
    }
}

__global__ void s_pack(const float* __restrict__ wh, const float* __restrict__ wi,
                       const float* __restrict__ w1, const float* __restrict__ w2,
                       const float* __restrict__ ew, const float* __restrict__ eb,
                       const float* __restrict__ bi, const unsigned char* __restrict__ eps) {
    int id = blockIdx.x * 256 + threadIdx.x;
    if (id < 98304) {
        // WG chunk layout (6 x 256 output cols):
        //  [0,768): Wh rows (r,z,n)
        //  [768,1280): comb = Wi+Wh rows (r,z)
        //  [1280,1536): Wi rows (n)
        int lane = id & 31, kt = (id >> 5) & 15, nt = id >> 9;
        int n = nt * 8 + (lane >> 2);
        const float* sa;
        const float* sb = 0;
        if (n < 768)        { sa = wh + n * 256; }
        else if (n < 1280)  { sa = wi + (n - 768) * 256; sb = wh + (n - 768) * 256; }
        else                { sa = wi + (n - 1280 + 512) * 256; }
        int k0 = kt * 16 + (lane & 3) * 2;
        float v0 = sa[k0]     + (sb ? sb[k0]     : 0.f);
        float v1 = sa[k0+1]   + (sb ? sb[k0+1]   : 0.f);
        float v2 = sa[k0+8]   + (sb ? sb[k0+8]   : 0.f);
        float v3 = sa[k0+9]   + (sb ? sb[k0+9]   : 0.f);
        uint2 H, L;
        H.x = packsplit(v0, v1, L.x);
        H.y = packsplit(v2, v3, L.y);
        d_WGhi[id] = H; d_WGlo[id] = L;
    } else if (id < 106496) {              // W1: [128,256]
        int j = id - 98304;
        int lane = j & 31, kt = (j >> 5) & 15, nt = j >> 9;
        const float* src = w1 + (nt * 8 + (lane >> 2)) * 256;
        int k0 = kt * 16 + (lane & 3) * 2;
        uint2 H, L;
        H.x = packsplit(src[k0],   src[k0+1], L.x);
        H.y = packsplit(src[k0+8], src[k0+9], L.y);
        d_W1hi[j] = H; d_W1lo[j] = L;
    } else if (id < 110592) {              // W2: [128,128]
        int j = id - 106496;
        int lane = j & 31, kt = (j >> 5) & 7, nt = j >> 8;
        const float* src = w2 + (nt * 8 + (lane >> 2)) * 128;
        int k0 = kt * 16 + (lane & 3) * 2;
        uint2 H, L;
        H.x = packsplit(src[k0],   src[k0+1], L.x);
        H.y = packsplit(src[k0+8], src[k0+9], L.y);
        d_W2hi[j] = H; d_W2lo[j] = L;
    } else if (id < 111360) {              // Mi = Wi@embed_w, ci = Wi@embed_b + bi
        int n = id - 110592;
        const float* wr = wi + n * 256;
        float m0 = 0.f, m1 = 0.f, cc = 0.f;
        for (int k = 0; k < 256; k++) {
            float v = wr[k];
            m0 += v * ew[2*k]; m1 += v * ew[2*k+1]; cc += v * eb[k];
        }
        d_Mi[2*n] = m0; d_Mi[2*n+1] = m1; d_ci[n] = cc + bi[n];
    } else if (id < 112640) {              // d_use[t][a]
        int j = id - 111360;
        int t = j >> 6, a = j & 63;
        unsigned char u = 0;
        if (t >= 8) {
            int m = (t - 8) * 64 + a;
            int mode = d_epsMode;
            float v = (mode == 2) ? ((const float*)eps)[m]
                    : (mode == 1) ? (float)((const int*)eps)[m]
                    : (float)eps[m];
            u = (v != 0.f) ? 1 : 0;
        }
        d_use[j] = u;
    }
}

// ---- fused GRU step: pipelined mma + gates + h update + fragment repack ----
// r/z gates: 1-term (A-hi x B-hi; sigmoid attenuates fp16 rounding).
// n gates:   2-term (A-hi+A-lo vs B-hi; state stays fp32-exact in the main path).
__global__ void __launch_bounds__(256, 2) k_step(const float* __restrict__ inp,
                                                 const float* __restrict__ bh,
                                                 const float* __restrict__ bi,
                                                 int t, int rb) {
    int am = blockIdx.x, cg = blockIdx.y, rz = blockIdx.z;
    int lane = threadIdx.x & 31, w = threadIdx.x >> 5;
    int wm = w & 1, wn = w >> 1;           // wn in 0..3
    bool full = d_use[t * 64 + am] != 0;
    const uint4* Ahi_r = (const uint4*)d_Ahi[rb];
    const uint4* Alo_r = (const uint4*)d_Alo[rb];
    unsigned* Ahi_w = d_Ahi[rb ^ 1];
    unsigned* Alo_w = d_Alo[rb ^ 1];

    int ntb = cg * 4 + wn;                 // n-tile within a 256-col chunk
    int chk0, chk1;
    if (full) { chk0 = 3; chk1 = 4; }      // comb_r, comb_z
    else      { chk0 = 0; chk1 = 1; }      // Wh_r, Wh_z
    int b0 = ((chk0 * 32 + ntb) * 16) * 32 + lane;
    int b1 = ((chk1 * 32 + ntb) * 16) * 32 + lane;
    int b2 = ((2    * 32 + ntb) * 16) * 32 + lane;   // Wh_n
    int b3 = ((5    * 32 + ntb) * 16) * 32 + lane;   // Wi_n

    int gmt0 = am * 8 + rz * 4 + wm * 2;
    int a0 = (gmt0 * 16) * 32 + lane;
    int a1 = ((gmt0 + 1) * 16) * 32 + lane;

    float acc[2][4][4];
#pragma unroll
    for (int i = 0; i < 2; i++)
#pragma unroll
        for (int j = 0; j < 4; j++)
#pragma unroll
            for (int q = 0; q < 4; q++) acc[i][j][q] = 0.f;

    // prologue: load kt=0
    uint4 ahC0 = Ahi_r[a0], ahC1 = Ahi_r[a1];
    uint4 alC0 = Alo_r[a0], alC1 = Alo_r[a1];
    uint2 bhC0 = d_WGhi[b0], bhC1 = d_WGhi[b1], bhC2 = d_WGhi[b2];
    uint2 bhC3 = make_uint2(0,0);
    if (full) bhC3 = d_WGhi[b3];

#pragma unroll 4
    for (int kt = 0; kt < 16; kt++) {
        int ktn = (kt + 1 < 16) ? (kt + 1) : 15;
        int o = ktn * 32;
        uint4 ahN0 = Ahi_r[a0 + o], ahN1 = Ahi_r[a1 + o];
        uint4 alN0 = Alo_r[a0 + o], alN1 = Alo_r[a1 + o];
        uint2 bhN0 = d_WGhi[b0 + o], bhN1 = d_WGhi[b1 + o], bhN2 = d_WGhi[b2 + o];
        uint2 bhN3;
        if (full) bhN3 = d_WGhi[b3 + o];

        // r gate (1-term), z gate (1-term)
        mma16816(acc[0][0], ahC0, bhC0); mma16816(acc[1][0], ahC1, bhC0);
        mma16816(acc[0][1], ahC0, bhC1); mma16816(acc[1][1], ahC1, bhC1);
        // n gate, h-side (2-term: A-hi + A-lo)
        mma16816(acc[0][2], ahC0, bhC2); mma16816(acc[1][2], ahC1, bhC2);
        mma16816(acc[0][2], alC0, bhC2); mma16816(acc[1][2], alC1, bhC2);
        if (full) {
            // n gate, i-side (2-term)
            mma16816(acc[0][3], ahC0, bhC3); mma16816(acc[1][3], ahC1, bhC3);
            mma16816(acc[0][3], alC0, bhC3); mma16816(acc[1][3], alC1, bhC3);
            bhC3 = bhN3;
        }
        ahC0 = ahN0; ahC1 = ahN1; alC0 = alN0; alC1 = alN1;
        bhC0 = bhN0; bhC1 = bhN1; bhC2 = bhN2;
    }

    // ---- gate epilogue (h_old reconstructed from fragments: hi+lo) ----
    int lane4 = lane >> 2;
    int c = cg * 32 + wn * 8 + (lane & 3) * 2;   // hidden col (even)
    float bhr0 = bh[c],       bhr1 = bh[c + 1];
    float bhz0 = bh[256 + c], bhz1 = bh[257 + c];
    float bhn0 = bh[512 + c], bhn1 = bh[513 + c];
    float bir0, bir1, biz0, biz1, bin0, bin1;
    float M0a[3], M0b[3], M1a[3], M1b[3], C0[3], C1[3];
    if (full) {
        bir0 = bi[c];       bir1 = bi[c + 1];
        biz0 = bi[256 + c]; biz1 = bi[257 + c];
        bin0 = bi[512 + c]; bin1 = bi[513 + c];
    } else {
#pragma unroll
        for (int g = 0; g < 3; g++) {
            int n0 = g * 256 + c;
            M0a[g] = d_Mi[2*n0];     M0b[g] = d_Mi[2*n0 + 1];   C0[g] = d_ci[n0];
            M1a[g] = d_Mi[2*n0 + 2]; M1b[g] = d_Mi[2*n0 + 3];   C1[g] = d_ci[n0 + 1];
        }
    }
    const unsigned* AhiU = (const unsigned*)Ahi_r;
    const unsigned* AloU = (const unsigned*)Alo_r;

#pragma unroll
    for (int i = 0; i < 2; i++) {
#pragma unroll
        for (int half = 0; half < 2; half++) {
            int r = (gmt0 + i) * 16 + half * 8 + lane4;
            int q0 = half * 2;
            int widx = fidx(r, c, 16);
            unsigned uh = AhiU[widx], ul = AloU[widx];
            __half2 hh = *(__half2*)&uh, hl = *(__half2*)&ul;
            float hox = __half2float(__low2half(hh))  + __half2float(__low2half(hl));
            float hoy = __half2float(__high2half(hh)) + __half2float(__high2half(hl));
            float r0g, r1g, z0g, z1g, n0g, n1g;
            if (full) {
                r0g = sigf(acc[i][0][q0]   + bir0 + bhr0);
                r1g = sigf(acc[i][0][q0+1] + bir1 + bhr1);
                z0g = sigf(acc[i][1][q0]   + biz0 + bhz0);
                z1g = sigf(acc[i][1][q0+1] + biz1 + bhz1);
                n0g = tanh_f(acc[i][3][q0]   + bin0 + r0g * (acc[i][2][q0]   + bhn0));
                n1g = tanh_f(acc[i][3][q0+1] + bin1 + r1g * (acc[i][2][q0+1] + bhn1));
            } else {
                int b = r & 127;
                const float* ip = inp + ((b * 64 + am) * 20 + t) * 2;
                float x0 = ip[0], x1 = ip[1];
                float ir0 = x0 * M0a[0] + x1 * M0b[0] + C0[0];
                float iz0 = x0 * M0a[1] + x1 * M0b[1] + C0[1];
                float in0 = x0 * M0a[2] + x1 * M0b[2] + C0[2];
                float ir1 = x0 * M1a[0] + x1 * M1b[0] + C1[0];
                float iz1 = x0 * M1a[1] + x1 * M1b[1] + C1[1];
                float in1 = x0 * M1a[2] + x1 * M1b[2] + C1[2];
                r0g = sigf(ir0 + acc[i][0][q0]   + bhr0);
                r1g = sigf(ir1 + acc[i][0][q0+1] + bhr1);
                z0g = sigf(iz0 + acc[i][1][q0]   + bhz0);
                z1g = sigf(iz1 + acc[i][1][q0+1] + bhz1);
                n0g = tanh_f(in0 + r0g * (acc[i][2][q0]   + bhn0));
                n1g = tanh_f(in1 + r1g * (acc[i][2][q0+1] + bhn1));
            }
            float h0 = (1.f - z0g) * n0g + z0g * hox;
            float h1 = (1.f - z1g) * n1g + z1g * hoy;
            unsigned lo, hi = packsplit(h0, h1, lo);
            Ahi_w[widx] = hi; Alo_w[widx] = lo;
        }
    }
}

// ---- fused FC head on 64 rows/CTA: fc1 -> smem frags -> fc2 -> smem -> fc3 ----
extern __shared__ unsigned smem_u[];
__global__ void __launch_bounds__(256) k_fc(const float* __restrict__ b1,
                                            const float* __restrict__ b2,
                                            const float* __restrict__ w3,
                                            const float* __restrict__ b3,
                                            const float* __restrict__ inp,
                                            float* __restrict__ out, int t, int rb) {
    unsigned* sY1hi = smem_u;          // 4096 u32
    unsigned* sY1lo = smem_u + 4096;   // 4096 u32
    float* sy2 = (float*)smem_u;       // 64*132 floats, overwrites after sync
    const uint4* Ahi_r = (const uint4*)d_Ahi[rb];
    const uint4* Alo_r = (const uint4*)d_Alo[rb];

    int lane = threadIdx.x & 31, w = threadIdx.x >> 5;
    int wm = w & 1, wn = w >> 1;
    int lane4 = lane >> 2;
    int agent = blockIdx.x >> 1, halfb = blockIdx.x & 1;
    int gmt0 = agent * 8 + halfb * 4 + wm * 2;

    // ---- fc1 ----
    float acc[2][4][4];
#pragma unroll
    for (int i = 0; i < 2; i++)
#pragma unroll
        for (int j = 0; j < 4; j++)
#pragma unroll
            for (int q = 0; q < 4; q++) acc[i][j][q] = 0.f;
#pragma unroll 2
    for (int kt = 0; kt < 16; kt++) {
        uint4 ah[2], al[2];
#pragma unroll
        for (int i = 0; i < 2; i++) {
            int base = ((gmt0 + i) * 16 + kt) * 32 + lane;
            ah[i] = Ahi_r[base];
            al[i] = Alo_r[base];
        }
#pragma unroll
        for (int j = 0; j < 4; j++) {
            int bb = ((wn * 4 + j) * 16 + kt) * 32 + lane;
            uint2 Bh = d_W1hi[bb], Bl = d_W1lo[bb];
#pragma unroll
            for (int i = 0; i < 2; i++) {
                mma16816(acc[i][j], ah[i], Bh);
                mma16816(acc[i][j], al[i], Bh);
                mma16816(acc[i][j], ah[i], Bl);
            }
        }
    }
#pragma unroll
    for (int i = 0; i < 2; i++)
#pragma unroll
        for (int j = 0; j < 4; j++) {
            int rr = wm * 32 + i * 16 + lane4;          // local row
            int cc = wn * 32 + j * 8 + (lane & 3) * 2;
            float bb0 = b1[cc], bb1 = b1[cc + 1];
            float v0 = eluf(acc[i][j][0] + bb0);
            float v1 = eluf(acc[i][j][1] + bb1);
            unsigned lo, hi = packsplit(v0, v1, lo);
            int widx = fidx(rr, cc, 8);
            sY1hi[widx] = hi; sY1lo[widx] = lo;
            v0 = eluf(acc[i][j][2] + bb0);
            v1 = eluf(acc[i][j][3] + bb1);
            hi = packsplit(v0, v1, lo);
            widx = fidx(rr + 8, cc, 8);
            sY1hi[widx] = hi; sY1lo[widx] = lo;
        }
    __syncthreads();

    // ---- fc2 ----
    float acc2[2][4][4];
#pragma unroll
    for (int i = 0; i < 2; i++)
#pragma unroll
        for (int j = 0; j < 4; j++)
#pragma unroll
            for (int q = 0; q < 4; q++) acc2[i][j][q] = 0.f;
    const uint4* sY1hi4 = (const uint4*)sY1hi;
    const uint4* sY1lo4 = (const uint4*)sY1lo;
#pragma unroll 2
    for (int kt = 0; kt < 8; kt++) {
        uint4 ah[2], al[2];
#pragma unroll
        for (int i = 0; i < 2; i++) {
            int base = ((wm * 2 + i) * 8 + kt) * 32 + lane;
            ah[i] = sY1hi4[base];
            al[i] = sY1lo4[base];
        }
#pragma unroll
        for (int j = 0; j < 4; j++) {
            int bb = ((wn * 4 + j) * 8 + kt) * 32 + lane;
            uint2 Bh = d_W2hi[bb], Bl = d_W2lo[bb];
#pragma unroll
            for (int i = 0; i < 2; i++) {
                mma16816(acc2[i][j], ah[i], Bh);
                mma16816(acc2[i][j], al[i], Bh);
                mma16816(acc2[i][j], ah[i], Bl);
            }
        }
    }
    __syncthreads();   // all sY1 reads done before overwrite with y2

#pragma unroll
    for (int i = 0; i < 2; i++)
#pragma unroll
        for (int j = 0; j < 4; j++) {
            int rr = wm * 32 + i * 16 + lane4;
            int cc = wn * 32 + j * 8 + (lane & 3) * 2;
            float bb0 = b2[cc], bb1 = b2[cc + 1];
            sy2[rr * 132 + cc]           = eluf(acc2[i][j][0] + bb0);
            sy2[rr * 132 + cc + 1]       = eluf(acc2[i][j][1] + bb1);
            sy2[(rr + 8) * 132 + cc]     = eluf(acc2[i][j][2] + bb0);
            sy2[(rr + 8) * 132 + cc + 1] = eluf(acc2[i][j][3] + bb1);
        }
    __syncthreads();

    // ---- fc3 + gt mask ----
    int tid = threadIdx.x;
    if (tid < 128) {
        int rl = tid >> 1, cr = tid & 1;
        const float* wr = w3 + cr * 128;
        float s = b3[cr];
#pragma unroll 8
        for (int k = 0; k < 128; k++) s += sy2[rl * 132 + k] * __ldg(wr + k);
        int b = halfb * 64 + rl;
        float gv = inp[((b * 64 + agent) * 20 + t) * 2 + cr];
        out[((b * 64 + agent) * 12 + (t - 8)) * 2 + cr] = (gv != 0.f) ? s : 0.f;
    }
}

extern "C" void kernel_launch(void* const* d_in, const int* in_sizes, int n_in,
                              void* d_out, int out_size) {
    int sh = (n_in >= 15 && in_sizes[1] <= 4) ? 0 : -1;
    const float* inputs = (const float*)d_in[0];
    const unsigned char* eps = (const unsigned char*)d_in[2 + sh];
    const float* ew = (const float*)d_in[3 + sh];
    const float* eb = (const float*)d_in[4 + sh];
    const float* wi = (const float*)d_in[5 + sh];
    const float* wh = (const float*)d_in[6 + sh];
    const float* bi = (const float*)d_in[7 + sh];
    const float* bh = (const float*)d_in[8 + sh];
    const float* w1 = (const float*)d_in[9 + sh];
    const float* b1 = (const float*)d_in[10 + sh];
    const float* w2 = (const float*)d_in[11 + sh];
    const float* b2 = (const float*)d_in[12 + sh];
    const float* w3 = (const float*)d_in[13 + sh];
    const float* b3 = (const float*)d_in[14 + sh];
    float* out = (float*)d_out;

    // side stream + events for overlapping the FC head with the recurrence
    static cudaStream_t s2 = 0;
    static cudaEvent_t evS = 0, evFc[2] = {0, 0};
    if (!s2) {
        cudaStreamCreateWithFlags(&s2, cudaStreamNonBlocking);
        cudaEventCreateWithFlags(&evS, cudaEventDisableTiming);
        cudaEventCreateWithFlags(&evFc[0], cudaEventDisableTiming);
        cudaEventCreateWithFlags(&evFc[1], cudaEventDisableTiming);
    }

    s_init<<<4096, 256>>>();
    s_detect<<<1, 32>>>(eps);
    s_pack<<<440, 256>>>(wh, wi, w1, w2, ew, eb, bi, eps);

    for (int t = 0; t < 20; t++) {
        // k_step(t) overwrites the buffer k_fc(t-2) reads: enforce ordering
        if (t >= 10) cudaStreamWaitEvent((cudaStream_t)0, evFc[t & 1], 0);
        k_step<<<dim3(64, 8, 2), 256>>>(inputs, bh, bi, t, t & 1);
        if (t >= 8) {
            cudaEventRecord(evS, (cudaStream_t)0);
            cudaStreamWaitEvent(s2, evS, 0);
            k_fc<<<128, 256, 34048, s2>>>(b1, b2, w3, b3, inputs, out, t, (t + 1) & 1);
            cudaEventRecord(evFc[t & 1], s2);
        }
    }
    // join the side stream back before capture/launch ends
    cudaStreamWaitEvent((cudaStream_t)0, evFc[0], 0);
    cudaStreamWaitEvent((cudaStream_t)0, evFc[1], 0);
}

// round 7
// speedup vs baseline: 2.6778x; 1.0124x over previous
#include <cuda_runtime.h>
#include <cuda_fp16.h>

#define RD 8192

// ---- static device scratch ----
__device__ unsigned d_Ahi[2][512*16*32*4];   // double-buffered h fragments (hi)
__device__ unsigned d_Alo[2][512*16*32*4];   // (lo)
__device__ uint2 d_WGhi[192*16*32];          // chunks: Wh_r,Wh_z,Wh_n,comb_r,comb_z,Wi_n
__device__ uint2 d_WGlo[192*16*32];
__device__ uint2 d_W1hi[16*16*32];
__device__ uint2 d_W1lo[16*16*32];
__device__ uint2 d_W2hi[16*8*32];
__device__ uint2 d_W2lo[16*8*32];
__device__ float d_Mi[768*2];
__device__ float d_ci[768];
__device__ unsigned char d_use[20*64];
__device__ int d_epsMode;

// ---- helpers ----
__device__ __forceinline__ unsigned packsplit(float v0, float v1, unsigned &lo) {
    __half h0 = __float2half(v0);
    __half h1 = __float2half(v1);
    __half l0 = __float2half(v0 - __half2float(h0));
    __half l1 = __float2half(v1 - __half2float(h1));
    lo = ((unsigned)__half_as_ushort(l1) << 16) | (unsigned)__half_as_ushort(l0);
    return ((unsigned)__half_as_ushort(h1) << 16) | (unsigned)__half_as_ushort(h0);
}
__device__ __forceinline__ int fidx(int r, int c, int KT) {
    return (((r >> 4) * KT + (c >> 4)) * 32 + (r & 7) * 4 + ((c & 7) >> 1)) * 4
           + ((r >> 3) & 1) + (((c >> 3) & 1) << 1);
}
__device__ __forceinline__ void mma16816(float (&c)[4], const uint4 a, const uint2 b) {
    asm volatile(
        "mma.sync.aligned.m16n8k16.row.col.f32.f16.f16.f32 "
        "{%0,%1,%2,%3},{%4,%5,%6,%7},{%8,%9},{%0,%1,%2,%3};\n"
        : "+f"(c[0]), "+f"(c[1]), "+f"(c[2]), "+f"(c[3])
        : "r"(a.x), "r"(a.y), "r"(a.z), "r"(a.w), "r"(b.x), "r"(b.y));
}
__device__ __forceinline__ float sigf(float x) {
    return __fdividef(1.f, 1.f + __expf(-x));
}
__device__ __forceinline__ float tanh_f(float x) {
    return 2.f * sigf(2.f * x) - 1.f;
}
__device__ __forceinline__ float eluf(float x) { return x > 0.f ? x : (__expf(x) - 1.f); }

// ---- setup ----
__global__ void s_init() {
    int i = blockIdx.x * 256 + threadIdx.x;
    if (i < 512*16*32*4) { d_Ahi[0][i] = 0u; d_Alo[0][i] = 0u; }
}

__global__ void s_detect(const unsigned char* eps) {
    if (threadIdx.x == 0 && blockIdx.x == 0) {
        int ones3f = 0, nz123 = 0;
        for (int i = 0; i < 768; i++) {
            unsigned char b = eps[i];
            if ((i & 3) == 3 && b == 0x3f) ones3f++;
            if ((i & 3) != 0 && b != 0) nz123++;
        }
        d_epsMode = (ones3f > 0) ? 2 : (nz123 == 0 ? 1 : 0);
    }
}

__global__ void s_pack(const float* __restrict__ wh, const float* __restrict__ wi,
                       const float* __restrict__ w1, const float* __restrict__ w2,
                       const float* __restrict__ ew, const float* __restrict__ eb,
                       const float* __restrict__ bi, const unsigned char* __restrict__ eps) {
    int id = blockIdx.x * 256 + threadIdx.x;
    if (id < 98304) {
        // WG chunk layout: [0,768): Wh r,z,n; [768,1280): Wi+Wh r,z; [1280,1536): Wi n
        int lane = id & 31, kt = (id >> 5) & 15, nt = id >> 9;
        int n = nt * 8 + (lane >> 2);
        const float* sa;
        const float* sb = 0;
        if (n < 768)        { sa = wh + n * 256; }
        else if (n < 1280)  { sa = wi + (n - 768) * 256; sb = wh + (n - 768) * 256; }
        else                { sa = wi + (n - 1280 + 512) * 256; }
        int k0 = kt * 16 + (lane & 3) * 2;
        float v0 = sa[k0]     + (sb ? sb[k0]     : 0.f);
        float v1 = sa[k0+1]   + (sb ? sb[k0+1]   : 0.f);
        float v2 = sa[k0+8]   + (sb ? sb[k0+8]   : 0.f);
        float v3 = sa[k0+9]   + (sb ? sb[k0+9]   : 0.f);
        uint2 H, L;
        H.x = packsplit(v0, v1, L.x);
        H.y = packsplit(v2, v3, L.y);
        d_WGhi[id] = H; d_WGlo[id] = L;
    } else if (id < 106496) {              // W1: [128,256]
        int j = id - 98304;
        int lane = j & 31, kt = (j >> 5) & 15, nt = j >> 9;
        const float* src = w1 + (nt * 8 + (lane >> 2)) * 256;
        int k0 = kt * 16 + (lane & 3) * 2;
        uint2 H, L;
        H.x = packsplit(src[k0],   src[k0+1], L.x);
        H.y = packsplit(src[k0+8], src[k0+9], L.y);
        d_W1hi[j] = H; d_W1lo[j] = L;
    } else if (id < 110592) {              // W2: [128,128]
        int j = id - 106496;
        int lane = j & 31, kt = (j >> 5) & 7, nt = j >> 8;
        const float* src = w2 + (nt * 8 + (lane >> 2)) * 128;
        int k0 = kt * 16 + (lane & 3) * 2;
        uint2 H, L;
        H.x = packsplit(src[k0],   src[k0+1], L.x);
        H.y = packsplit(src[k0+8], src[k0+9], L.y);
        d_W2hi[j] = H; d_W2lo[j] = L;
    } else if (id < 111360) {              // Mi = Wi@embed_w, ci = Wi@embed_b + bi
        int n = id - 110592;
        const float* wr = wi + n * 256;
        float m0 = 0.f, m1 = 0.f, cc = 0.f;
        for (int k = 0; k < 256; k++) {
            float v = wr[k];
            m0 += v * ew[2*k]; m1 += v * ew[2*k+1]; cc += v * eb[k];
        }
        d_Mi[2*n] = m0; d_Mi[2*n+1] = m1; d_ci[n] = cc + bi[n];
    } else if (id < 112640) {              // d_use[t][a]
        int j = id - 111360;
        int t = j >> 6, a = j & 63;
        unsigned char u = 0;
        if (t >= 8) {
            int m = (t - 8) * 64 + a;
            int mode = d_epsMode;
            float v = (mode == 2) ? ((const float*)eps)[m]
                    : (mode == 1) ? (float)((const int*)eps)[m]
                    : (float)eps[m];
            u = (v != 0.f) ? 1 : 0;
        }
        d_use[j] = u;
    }
}

// ---- fused GRU step: warp covers 2 m-tiles x 2 n-tiles x 4 gate chunks ----
// r/z: 1-term; n: 2-term (A-hi + A-lo). A double-buffered, B single (L1-hot).
__global__ void __launch_bounds__(256, 2) k_step(const float* __restrict__ inp,
                                                 const float* __restrict__ bh,
                                                 const float* __restrict__ bi,
                                                 int t, int rb) {
    int am = blockIdx.x, cg = blockIdx.y, rz = blockIdx.z;
    int lane = threadIdx.x & 31, w = threadIdx.x >> 5;
    int wm = w & 1, wn = w >> 1;           // wn in 0..3
    bool full = d_use[t * 64 + am] != 0;
    const uint4* Ahi_r = (const uint4*)d_Ahi[rb];
    const uint4* Alo_r = (const uint4*)d_Alo[rb];
    unsigned* Ahi_w = d_Ahi[rb ^ 1];
    unsigned* Alo_w = d_Alo[rb ^ 1];

    int nt0 = cg * 8 + wn * 2;             // first of two n-tiles (of 32 per chunk)
    int chkR, chkZ;
    if (full) { chkR = 3; chkZ = 4; }      // comb_r, comb_z
    else      { chkR = 0; chkZ = 1; }      // Wh_r, Wh_z
    // uint2 index bases (nt adds 512 = 16*32)
    int bR = ((chkR * 32 + nt0) * 16) * 32 + lane;
    int bZ = ((chkZ * 32 + nt0) * 16) * 32 + lane;
    int bN = ((2    * 32 + nt0) * 16) * 32 + lane;   // Wh_n
    int bI = ((5    * 32 + nt0) * 16) * 32 + lane;   // Wi_n

    int gmt0 = am * 8 + rz * 4 + wm * 2;
    int a0 = (gmt0 * 16) * 32 + lane;
    int a1 = ((gmt0 + 1) * 16) * 32 + lane;

    float acc[2][2][4][4];                 // [mt][nt][gate r,z,nh,ni][4]
#pragma unroll
    for (int i = 0; i < 2; i++)
#pragma unroll
        for (int n = 0; n < 2; n++)
#pragma unroll
            for (int g = 0; g < 4; g++)
#pragma unroll
                for (int q = 0; q < 4; q++) acc[i][n][g][q] = 0.f;

    // prologue: A for kt=0
    uint4 ahC0 = Ahi_r[a0], ahC1 = Ahi_r[a1];
    uint4 alC0 = Alo_r[a0], alC1 = Alo_r[a1];

#pragma unroll 4
    for (int kt = 0; kt < 16; kt++) {
        int ob = kt * 32;
        // B loads for current kt (issued first to give them slack)
        uint2 Br0 = d_WGhi[bR + ob],       Br1 = d_WGhi[bR + ob + 512];
        uint2 Bz0 = d_WGhi[bZ + ob],       Bz1 = d_WGhi[bZ + ob + 512];
        uint2 Bn0 = d_WGhi[bN + ob],       Bn1 = d_WGhi[bN + ob + 512];
        uint2 Bi0, Bi1;
        if (full) { Bi0 = d_WGhi[bI + ob]; Bi1 = d_WGhi[bI + ob + 512]; }
        // A prefetch for kt+1
        int o = ((kt + 1 < 16) ? (kt + 1) : 15) * 32;
        uint4 ahN0 = Ahi_r[a0 + o], ahN1 = Ahi_r[a1 + o];
        uint4 alN0 = Alo_r[a0 + o], alN1 = Alo_r[a1 + o];

        mma16816(acc[0][0][0], ahC0, Br0); mma16816(acc[1][0][0], ahC1, Br0);
        mma16816(acc[0][1][0], ahC0, Br1); mma16816(acc[1][1][0], ahC1, Br1);
        mma16816(acc[0][0][1], ahC0, Bz0); mma16816(acc[1][0][1], ahC1, Bz0);
        mma16816(acc[0][1][1], ahC0, Bz1); mma16816(acc[1][1][1], ahC1, Bz1);
        mma16816(acc[0][0][2], ahC0, Bn0); mma16816(acc[1][0][2], ahC1, Bn0);
        mma16816(acc[0][1][2], ahC0, Bn1); mma16816(acc[1][1][2], ahC1, Bn1);
        mma16816(acc[0][0][2], alC0, Bn0); mma16816(acc[1][0][2], alC1, Bn0);
        mma16816(acc[0][1][2], alC0, Bn1); mma16816(acc[1][1][2], alC1, Bn1);
        if (full) {
            mma16816(acc[0][0][3], ahC0, Bi0); mma16816(acc[1][0][3], ahC1, Bi0);
            mma16816(acc[0][1][3], ahC0, Bi1); mma16816(acc[1][1][3], ahC1, Bi1);
            mma16816(acc[0][0][3], alC0, Bi0); mma16816(acc[1][0][3], alC1, Bi0);
            mma16816(acc[0][1][3], alC0, Bi1); mma16816(acc[1][1][3], alC1, Bi1);
        }
        ahC0 = ahN0; ahC1 = ahN1; alC0 = alN0; alC1 = alN1;
    }

    // ---- gate epilogue (h_old reconstructed from fragments: hi+lo) ----
    int lane4 = lane >> 2;
    // per-nt column constants
    float bhr0[2], bhr1[2], bhz0[2], bhz1[2], bhn0[2], bhn1[2];
    float bir0[2], bir1[2], biz0[2], biz1[2], bin0[2], bin1[2];
    float M0a[2][3], M0b[2][3], M1a[2][3], M1b[2][3], C0[2][3], C1[2][3];
    int cc[2];
#pragma unroll
    for (int n = 0; n < 2; n++) {
        int c = (nt0 + n) * 8 + (lane & 3) * 2;
        cc[n] = c;
        bhr0[n] = bh[c];       bhr1[n] = bh[c + 1];
        bhz0[n] = bh[256 + c]; bhz1[n] = bh[257 + c];
        bhn0[n] = bh[512 + c]; bhn1[n] = bh[513 + c];
        if (full) {
            bir0[n] = bi[c];       bir1[n] = bi[c + 1];
            biz0[n] = bi[256 + c]; biz1[n] = bi[257 + c];
            bin0[n] = bi[512 + c]; bin1[n] = bi[513 + c];
        } else {
#pragma unroll
            for (int g = 0; g < 3; g++) {
                int n0 = g * 256 + c;
                M0a[n][g] = d_Mi[2*n0];     M0b[n][g] = d_Mi[2*n0 + 1];   C0[n][g] = d_ci[n0];
                M1a[n][g] = d_Mi[2*n0 + 2]; M1b[n][g] = d_Mi[2*n0 + 3];   C1[n][g] = d_ci[n0 + 1];
            }
        }
    }
    const unsigned* AhiU = (const unsigned*)Ahi_r;
    const unsigned* AloU = (const unsigned*)Alo_r;

#pragma unroll
    for (int i = 0; i < 2; i++) {
#pragma unroll
        for (int half = 0; half < 2; half++) {
            int r = (gmt0 + i) * 16 + half * 8 + lane4;
            int q0 = half * 2;
            float x0 = 0.f, x1 = 0.f;
            if (!full) {
                int b = r & 127;
                const float* ip = inp + ((b * 64 + am) * 20 + t) * 2;
                x0 = ip[0]; x1 = ip[1];
            }
#pragma unroll
            for (int n = 0; n < 2; n++) {
                int c = cc[n];
                int widx = fidx(r, c, 16);
                unsigned uh = AhiU[widx], ul = AloU[widx];
                __half2 hh = *(__half2*)&uh, hl = *(__half2*)&ul;
                float hox = __half2float(__low2half(hh))  + __half2float(__low2half(hl));
                float hoy = __half2float(__high2half(hh)) + __half2float(__high2half(hl));
                float r0g, r1g, z0g, z1g, n0g, n1g;
                if (full) {
                    r0g = sigf(acc[i][n][0][q0]   + bir0[n] + bhr0[n]);
                    r1g = sigf(acc[i][n][0][q0+1] + bir1[n] + bhr1[n]);
                    z0g = sigf(acc[i][n][1][q0]   + biz0[n] + bhz0[n]);
                    z1g = sigf(acc[i][n][1][q0+1] + biz1[n] + bhz1[n]);
                    n0g = tanh_f(acc[i][n][3][q0]   + bin0[n] + r0g * (acc[i][n][2][q0]   + bhn0[n]));
                    n1g = tanh_f(acc[i][n][3][q0+1] + bin1[n] + r1g * (acc[i][n][2][q0+1] + bhn1[n]));
                } else {
                    float ir0 = x0 * M0a[n][0] + x1 * M0b[n][0] + C0[n][0];
                    float iz0 = x0 * M0a[n][1] + x1 * M0b[n][1] + C0[n][1];
                    float in0 = x0 * M0a[n][2] + x1 * M0b[n][2] + C0[n][2];
                    float ir1 = x0 * M1a[n][0] + x1 * M1b[n][0] + C1[n][0];
                    float iz1 = x0 * M1a[n][1] + x1 * M1b[n][1] + C1[n][1];
                    float in1 = x0 * M1a[n][2] + x1 * M1b[n][2] + C1[n][2];
                    r0g = sigf(ir0 + acc[i][n][0][q0]   + bhr0[n]);
                    r1g = sigf(ir1 + acc[i][n][0][q0+1] + bhr1[n]);
                    z0g = sigf(iz0 + acc[i][n][1][q0]   + bhz0[n]);
                    z1g = sigf(iz1 + acc[i][n][1][q0+1] + bhz1[n]);
                    n0g = tanh_f(in0 + r0g * (acc[i][n][2][q0]   + bhn0[n]));
                    n1g = tanh_f(in1 + r1g * (acc[i][n][2][q0+1] + bhn1[n]));
                }
                float h0 = (1.f - z0g) * n0g + z0g * hox;
                float h1 = (1.f - z1g) * n1g + z1g * hoy;
                unsigned lo, hi = packsplit(h0, h1, lo);
                Ahi_w[widx] = hi; Alo_w[widx] = lo;
            }
        }
    }
}

// ---- fused FC head on 64 rows/CTA: fc1 -> smem frags -> fc2 -> smem -> fc3 ----
extern __shared__ unsigned smem_u[];
__global__ void __launch_bounds__(256) k_fc(const float* __restrict__ b1,
                                            const float* __restrict__ b2,
                                            const float* __restrict__ w3,
                                            const float* __restrict__ b3,
                                            const float* __restrict__ inp,
                                            float* __restrict__ out, int t, int rb) {
    unsigned* sY1hi = smem_u;          // 4096 u32
    unsigned* sY1lo = smem_u + 4096;   // 4096 u32
    float* sy2 = (float*)smem_u;       // 64*132 floats, overwrites after sync
    const uint4* Ahi_r = (const uint4*)d_Ahi[rb];
    const uint4* Alo_r = (const uint4*)d_Alo[rb];

    int lane = threadIdx.x & 31, w = threadIdx.x >> 5;
    int wm = w & 1, wn = w >> 1;
    int lane4 = lane >> 2;
    int agent = blockIdx.x >> 1, halfb = blockIdx.x & 1;
    int gmt0 = agent * 8 + halfb * 4 + wm * 2;

    // ---- fc1 ----
    float acc[2][4][4];
#pragma unroll
    for (int i = 0; i < 2; i++)
#pragma unroll
        for (int j = 0; j < 4; j++)
#pragma unroll
            for (int q = 0; q < 4; q++) acc[i][j][q] = 0.f;
#pragma unroll 2
    for (int kt = 0; kt < 16; kt++) {
        uint4 ah[2], al[2];
#pragma unroll
        for (int i = 0; i < 2; i++) {
            int base = ((gmt0 + i) * 16 + kt) * 32 + lane;
            ah[i] = Ahi_r[base];
            al[i] = Alo_r[base];
        }
#pragma unroll
        for (int j = 0; j < 4; j++) {
            int bb = ((wn * 4 + j) * 16 + kt) * 32 + lane;
            uint2 Bh = d_W1hi[bb], Bl = d_W1lo[bb];
#pragma unroll
            for (int i = 0; i < 2; i++) {
                mma16816(acc[i][j], ah[i], Bh);
                mma16816(acc[i][j], al[i], Bh);
                mma16816(acc[i][j], ah[i], Bl);
            }
        }
    }
#pragma unroll
    for (int i = 0; i < 2; i++)
#pragma unroll
        for (int j = 0; j < 4; j++) {
            int rr = wm * 32 + i * 16 + lane4;          // local row
            int cc = wn * 32 + j * 8 + (lane & 3) * 2;
            float bb0 = b1[cc], bb1 = b1[cc + 1];
            float v0 = eluf(acc[i][j][0] + bb0);
            float v1 = eluf(acc[i][j][1] + bb1);
            unsigned lo, hi = packsplit(v0, v1, lo);
            int widx = fidx(rr, cc, 8);
            sY1hi[widx] = hi; sY1lo[widx] = lo;
            v0 = eluf(acc[i][j][2] + bb0);
            v1 = eluf(acc[i][j][3] + bb1);
            hi = packsplit(v0, v1, lo);
            widx = fidx(rr + 8, cc, 8);
            sY1hi[widx] = hi; sY1lo[widx] = lo;
        }
    __syncthreads();

    // ---- fc2 ----
    float acc2[2][4][4];
#pragma unroll
    for (int i = 0; i < 2; i++)
#pragma unroll
        for (int j = 0; j < 4; j++)
#pragma unroll
            for (int q = 0; q < 4; q++) acc2[i][j][q] = 0.f;
    const uint4* sY1hi4 = (const uint4*)sY1hi;
    const uint4* sY1lo4 = (const uint4*)sY1lo;
#pragma unroll 2
    for (int kt = 0; kt < 8; kt++) {
        uint4 ah[2], al[2];
#pragma unroll
        for (int i = 0; i < 2; i++) {
            int base = ((wm * 2 + i) * 8 + kt) * 32 + lane;
            ah[i] = sY1hi4[base];
            al[i] = sY1lo4[base];
        }
#pragma unroll
        for (int j = 0; j < 4; j++) {
            int bb = ((wn * 4 + j) * 8 + kt) * 32 + lane;
            uint2 Bh = d_W2hi[bb], Bl = d_W2lo[bb];
#pragma unroll
            for (int i = 0; i < 2; i++) {
                mma16816(acc2[i][j], ah[i], Bh);
                mma16816(acc2[i][j], al[i], Bh);
                mma16816(acc2[i][j], ah[i], Bl);
            }
        }
    }
    __syncthreads();   // all sY1 reads done before overwrite with y2

#pragma unroll
    for (int i = 0; i < 2; i++)
#pragma unroll
        for (int j = 0; j < 4; j++) {
            int rr = wm * 32 + i * 16 + lane4;
            int cc = wn * 32 + j * 8 + (lane & 3) * 2;
            float bb0 = b2[cc], bb1 = b2[cc + 1];
            sy2[rr * 132 + cc]           = eluf(acc2[i][j][0] + bb0);
            sy2[rr * 132 + cc + 1]       = eluf(acc2[i][j][1] + bb1);
            sy2[(rr + 8) * 132 + cc]     = eluf(acc2[i][j][2] + bb0);
            sy2[(rr + 8) * 132 + cc + 1] = eluf(acc2[i][j][3] + bb1);
        }
    __syncthreads();

    // ---- fc3 + gt mask ----
    int tid = threadIdx.x;
    if (tid < 128) {
        int rl = tid >> 1, cr = tid & 1;
        const float* wr = w3 + cr * 128;
        float s = b3[cr];
#pragma unroll 8
        for (int k = 0; k < 128; k++) s += sy2[rl * 132 + k] * __ldg(wr + k);
        int b = halfb * 64 + rl;
        float gv = inp[((b * 64 + agent) * 20 + t) * 2 + cr];
        out[((b * 64 + agent) * 12 + (t - 8)) * 2 + cr] = (gv != 0.f) ? s : 0.f;
    }
}

extern "C" void kernel_launch(void* const* d_in, const int* in_sizes, int n_in,
                              void* d_out, int out_size) {
    int sh = (n_in >= 15 && in_sizes[1] <= 4) ? 0 : -1;
    const float* inputs = (const float*)d_in[0];
    const unsigned char* eps = (const unsigned char*)d_in[2 + sh];
    const float* ew = (const float*)d_in[3 + sh];
    const float* eb = (const float*)d_in[4 + sh];
    const float* wi = (const float*)d_in[5 + sh];
    const float* wh = (const float*)d_in[6 + sh];
    const float* bi = (const float*)d_in[7 + sh];
    const float* bh = (const float*)d_in[8 + sh];
    const float* w1 = (const float*)d_in[9 + sh];
    const float* b1 = (const float*)d_in[10 + sh];
    const float* w2 = (const float*)d_in[11 + sh];
    const float* b2 = (const float*)d_in[12 + sh];
    const float* w3 = (const float*)d_in[13 + sh];
    const float* b3 = (const float*)d_in[14 + sh];
    float* out = (float*)d_out;

    // side stream + events for overlapping the FC head with the recurrence
    static cudaStream_t s2 = 0;
    static cudaEvent_t evS = 0, evFc[2] = {0, 0};
    if (!s2) {
        cudaStreamCreateWithFlags(&s2, cudaStreamNonBlocking);
        cudaEventCreateWithFlags(&evS, cudaEventDisableTiming);
        cudaEventCreateWithFlags(&evFc[0], cudaEventDisableTiming);
        cudaEventCreateWithFlags(&evFc[1], cudaEventDisableTiming);
    }

    s_init<<<4096, 256>>>();
    s_detect<<<1, 32>>>(eps);
    s_pack<<<440, 256>>>(wh, wi, w1, w2, ew, eb, bi, eps);

    for (int t = 0; t < 20; t++) {
        // k_step(t) overwrites the buffer k_fc(t-2) reads: enforce ordering
        if (t >= 10) cudaStreamWaitEvent((cudaStream_t)0, evFc[t & 1], 0);
        k_step<<<dim3(64, 4, 2), 256>>>(inputs, bh, bi, t, t & 1);
        if (t >= 8) {
            cudaEventRecord(evS, (cudaStream_t)0);
            cudaStreamWaitEvent(s2, evS, 0);
            k_fc<<<128, 256, 34048, s2>>>(b1, b2, w3, b3, inputs, out, t, (t + 1) & 1);
            cudaEventRecord(evFc[t & 1], s2);
        }
    }
    // join the side stream back before capture/launch ends
    cudaStreamWaitEvent((cudaStream_t)0, evFc[0], 0);
    cudaStreamWaitEvent((cudaStream_t)0, evFc[1], 0);
}